// round 14
// baseline (speedup 1.0000x reference)
#include <cuda_runtime.h>
#include <cuda_bf16.h>
#include <math.h>
#include <stdint.h>

#define NSEQ 2048
#define BATCH 2
#define NHEAD 16
#define MROWS 4096
#define WINR 128
#define ASCALE 0.125f

typedef unsigned long long u64;
struct P3 { const float* a; const float* b; const float* c; };
__device__ __forceinline__ const float* sel(P3 p, int i) {
    return i == 0 ? p.a : (i == 1 ? p.b : p.c);
}

__device__ __forceinline__ u64 PK2(float lo, float hi) {
    u64 r; asm("mov.b64 %0,{%1,%2};" : "=l"(r) : "f"(lo), "f"(hi)); return r;
}
__device__ __forceinline__ u64 DUP(float v) { return PK2(v, v); }
__device__ __forceinline__ void FMA2(u64& d, u64 a, u64 b) {
    asm("fma.rn.f32x2 %0,%1,%2,%0;" : "+l"(d) : "l"(a), "l"(b));
}
__device__ __forceinline__ float2 UPK(u64 v) {
    float2 f; asm("mov.b64 {%0,%1},%2;" : "=f"(f.x), "=f"(f.y) : "l"(v)); return f;
}

__device__ __forceinline__ uint32_t smem_u32(const void* p) {
    uint32_t a;
    asm("{ .reg .u64 t; cvta.to.shared.u64 t, %1; cvt.u32.u64 %0, t; }" : "=r"(a) : "l"(p));
    return a;
}

// ---- portable tensor-core + async-copy ops (sm_80+ baseline PTX) ----
__device__ __forceinline__ void MMA_BF16(float* d, const uint32_t* a, uint32_t b0, uint32_t b1) {
    asm volatile(
        "mma.sync.aligned.m16n8k16.row.col.f32.bf16.bf16.f32 "
        "{%0,%1,%2,%3}, {%4,%5,%6,%7}, {%8,%9}, {%0,%1,%2,%3};"
        : "+f"(d[0]), "+f"(d[1]), "+f"(d[2]), "+f"(d[3])
        : "r"(a[0]), "r"(a[1]), "r"(a[2]), "r"(a[3]), "r"(b0), "r"(b1));
}
__device__ __forceinline__ void LDSM4(uint32_t* r, uint32_t addr) {
    asm volatile("ldmatrix.sync.aligned.m8n8.x4.shared.b16 {%0,%1,%2,%3}, [%4];"
                 : "=r"(r[0]), "=r"(r[1]), "=r"(r[2]), "=r"(r[3]) : "r"(addr));
}
__device__ __forceinline__ void LDSM4T(uint32_t* r, uint32_t addr) {
    asm volatile("ldmatrix.sync.aligned.m8n8.x4.trans.shared.b16 {%0,%1,%2,%3}, [%4];"
                 : "=r"(r[0]), "=r"(r[1]), "=r"(r[2]), "=r"(r[3]) : "r"(addr));
}
__device__ __forceinline__ uint32_t CVT2(float lo, float hi) {
    uint32_t r; asm("cvt.rn.bf16x2.f32 %0, %1, %2;" : "=r"(r) : "f"(hi), "f"(lo)); return r;
}
#define CP_ASYNC16(dst, src) \
    asm volatile("cp.async.ca.shared.global [%0], [%1], 16;" :: "r"(dst), "l"(src) : "memory")
#define CP_COMMIT() asm volatile("cp.async.commit_group;" ::: "memory")
#define CP_WAIT(n)  asm volatile("cp.async.wait_group %0;" :: "n"(n) : "memory")

// ---------------- scratch ----------------
__device__ float g_t[3 * MROWS * 64];
__device__ float g_l[3 * MROWS * 4];
__device__ float g_qkv[3 * BATCH * NHEAD * NSEQ * 64];
__device__ float g_comb[BATCH * NHEAD * NSEQ * 64];
__device__ __nv_bfloat16 g_wh[1024 * 1024];
__device__ __nv_bfloat16 g_wl[1024 * 1024];

// ---------------------------------------------------------------------------
// t = x @ U * alpha.  64x64 tile, 128 thr, 8x4 micro (R10 version).
// ---------------------------------------------------------------------------
__global__ __launch_bounds__(128) void k_xu(const float* __restrict__ X,
                                            P3 Us, P3 als, float* __restrict__ Tb) {
    __shared__ float a_s[64][68];
    __shared__ float b_s[64][68];
    int p = blockIdx.y;
    const float* U = sel(Us, p);
    const float* alpha = sel(als, p);
    float* T = Tb + (size_t)p * MROWS * 64;
    int t = threadIdx.x;
    int m0 = blockIdx.x * 64;
    int tm = t >> 4, tn4 = t & 15;
    u64 acc2[8][2] = {};
    for (int k0 = 0; k0 < 1024; k0 += 64) {
#pragma unroll
        for (int rep = 0; rep < 8; rep++) {
            int fidx = t + rep * 128;
            int m = fidx >> 4, kq = fidx & 15;
            float4 v = *(const float4*)&X[(size_t)(m0 + m) * 1024 + k0 + kq * 4];
            a_s[kq * 4 + 0][m] = v.x; a_s[kq * 4 + 1][m] = v.y;
            a_s[kq * 4 + 2][m] = v.z; a_s[kq * 4 + 3][m] = v.w;
        }
#pragma unroll
        for (int rep = 0; rep < 8; rep++) {
            int fidx = t + rep * 128;
            int kk = fidx >> 4, nq = fidx & 15;
            *(float4*)&b_s[kk][nq * 4] = *(const float4*)&U[(size_t)(k0 + kk) * 64 + nq * 4];
        }
        __syncthreads();
#pragma unroll 8
        for (int kk = 0; kk < 64; kk++) {
            float4 a0 = *(const float4*)&a_s[kk][tm * 8];
            float4 a1 = *(const float4*)&a_s[kk][tm * 8 + 4];
            ulonglong2 bp = *(const ulonglong2*)&b_s[kk][tn4 * 4];
            float aa[8] = {a0.x, a0.y, a0.z, a0.w, a1.x, a1.y, a1.z, a1.w};
#pragma unroll
            for (int i = 0; i < 8; i++) {
                u64 d = DUP(aa[i]);
                FMA2(acc2[i][0], d, bp.x);
                FMA2(acc2[i][1], d, bp.y);
            }
        }
        __syncthreads();
    }
    float al0 = alpha[tn4 * 4 + 0], al1 = alpha[tn4 * 4 + 1];
    float al2 = alpha[tn4 * 4 + 2], al3 = alpha[tn4 * 4 + 3];
#pragma unroll
    for (int i = 0; i < 8; i++) {
        float2 c0 = UPK(acc2[i][0]), c1 = UPK(acc2[i][1]);
        float4 o = make_float4(c0.x * al0, c0.y * al1, c1.x * al2, c1.y * al3);
        *(float4*)&T[(size_t)(m0 + tm * 8 + i) * 64 + tn4 * 4] = o;
    }
}

// ---------------------------------------------------------------------------
// l = x @ A (12 cols fused).
// ---------------------------------------------------------------------------
__global__ __launch_bounds__(128) void k_lora(const float* __restrict__ X,
                                              P3 As, float* __restrict__ Lb) {
    int m = blockIdx.x;
    int t = threadIdx.x;
    float p[12] = {};
    const float* A0 = As.a; const float* A1 = As.b; const float* A2 = As.c;
    for (int k = t; k < 1024; k += 128) {
        float xv = X[(size_t)m * 1024 + k];
#pragma unroll
        for (int j = 0; j < 4; j++) {
            p[j]     += xv * A0[k * 4 + j];
            p[4 + j] += xv * A1[k * 4 + j];
            p[8 + j] += xv * A2[k * 4 + j];
        }
    }
    __shared__ float red[12][128];
#pragma unroll
    for (int j = 0; j < 12; j++) red[j][t] = p[j];
    __syncthreads();
    for (int s = 64; s > 0; s >>= 1) {
        if (t < s) {
#pragma unroll
            for (int j = 0; j < 12; j++) red[j][t] += red[j][t + s];
        }
        __syncthreads();
    }
    if (t < 12) {
        int pr = t >> 2, j = t & 3;
        Lb[(size_t)pr * MROWS * 4 + (size_t)m * 4 + j] = red[t][0];
    }
}

// ---------------------------------------------------------------------------
// proj: out = [t | l] @ [V^T ; Blora] + bias -> [B,H,N,HD].
// ---------------------------------------------------------------------------
__global__ __launch_bounds__(256, 2) void k_proj(const float* __restrict__ Tb,
                                                 const float* __restrict__ Lb,
                                                 P3 Vs, P3 Bls, P3 bis,
                                                 float* __restrict__ QKV) {
    __shared__ float a_s[68][132];
    __shared__ float b_s[68][132];
    int p = blockIdx.z;
    const float* T = Tb + (size_t)p * MROWS * 64;
    const float* L = Lb + (size_t)p * MROWS * 4;
    const float* V = sel(Vs, p);
    const float* Blora = sel(Bls, p);
    const float* bias = sel(bis, p);
    float* O = QKV + (size_t)p * BATCH * NHEAD * NSEQ * 64;

    int t = threadIdx.x;
    int m0 = blockIdx.x * 128;
    int n0 = blockIdx.y * 128;
    int tq = t >> 4, tn = t & 15;

#pragma unroll
    for (int rep = 0; rep < 8; rep++) {
        int fidx = t + rep * 256;
        int m = fidx >> 4, kq = fidx & 15;
        float4 v = *(const float4*)&T[(size_t)(m0 + m) * 64 + kq * 4];
        a_s[kq * 4 + 0][m] = v.x; a_s[kq * 4 + 1][m] = v.y;
        a_s[kq * 4 + 2][m] = v.z; a_s[kq * 4 + 3][m] = v.w;
    }
    if (t < 128) {
        float4 lv = *(const float4*)&L[(size_t)(m0 + t) * 4];
        a_s[64][t] = lv.x; a_s[65][t] = lv.y; a_s[66][t] = lv.z; a_s[67][t] = lv.w;
    }
#pragma unroll
    for (int rep = 0; rep < 8; rep++) {
        int fidx = t + rep * 256;
        int n = fidx >> 4, kq = fidx & 15;
        float4 v = *(const float4*)&V[(size_t)(n0 + n) * 64 + kq * 4];
        b_s[kq * 4 + 0][n] = v.x; b_s[kq * 4 + 1][n] = v.y;
        b_s[kq * 4 + 2][n] = v.z; b_s[kq * 4 + 3][n] = v.w;
    }
#pragma unroll
    for (int rep = 0; rep < 2; rep++) {
        int idx = t + rep * 256;
        int j = idx >> 7, n = idx & 127;
        b_s[64 + j][n] = Blora[(size_t)j * 1024 + n0 + n];
    }
    __syncthreads();

    u64 acc2[8][4] = {};
#pragma unroll 4
    for (int kk = 0; kk < 68; kk++) {
        float4 a0 = *(const float4*)&a_s[kk][tq * 8];
        float4 a1 = *(const float4*)&a_s[kk][tq * 8 + 4];
        ulonglong2 bp0 = *(const ulonglong2*)&b_s[kk][tn * 8];
        ulonglong2 bp1 = *(const ulonglong2*)&b_s[kk][tn * 8 + 4];
        float aa[8] = {a0.x, a0.y, a0.z, a0.w, a1.x, a1.y, a1.z, a1.w};
#pragma unroll
        for (int i = 0; i < 8; i++) {
            u64 d = DUP(aa[i]);
            FMA2(acc2[i][0], d, bp0.x); FMA2(acc2[i][1], d, bp0.y);
            FMA2(acc2[i][2], d, bp1.x); FMA2(acc2[i][3], d, bp1.y);
        }
    }

    int ng = n0 + tn * 8;
    int h = ng >> 6, hd0 = ng & 63;
    float bb[8];
#pragma unroll
    for (int j = 0; j < 8; j++) bb[j] = bias[ng + j];
#pragma unroll
    for (int i = 0; i < 8; i++) {
        int m = m0 + tq * 8 + i;
        int bi = m >> 11, ni = m & 2047;
        size_t base = ((size_t)(bi * 16 + h) * 2048 + ni) * 64 + hd0;
        float2 c0 = UPK(acc2[i][0]), c1 = UPK(acc2[i][1]);
        float2 c2 = UPK(acc2[i][2]), c3 = UPK(acc2[i][3]);
        float4 o0 = make_float4(c0.x + bb[0], c0.y + bb[1], c1.x + bb[2], c1.y + bb[3]);
        float4 o1 = make_float4(c2.x + bb[4], c2.y + bb[5], c3.x + bb[6], c3.y + bb[7]);
        *(float4*)&O[base + 0] = o0;
        *(float4*)&O[base + 4] = o1;
    }
}

// ---------------------------------------------------------------------------
// fused 3-branch flash attention via mma.sync bf16x3 (R7/R10 verbatim).
// ---------------------------------------------------------------------------
__global__ __launch_bounds__(128) void k_attn_mma(const float* __restrict__ Q,
                                                  const float* __restrict__ K,
                                                  const float* __restrict__ V,
                                                  const float* __restrict__ MEMV,
                                                  float* __restrict__ O) {
    extern __shared__ char sma[];
    char* KH = sma;
    char* KL = sma + 8192;
    char* VH = sma + 16384;
    char* VL = sma + 24576;
    uint32_t sKH = smem_u32(KH), sKL = smem_u32(KL);
    uint32_t sVH = smem_u32(VH), sVL = smem_u32(VL);

    int t = threadIdx.x;
    int w = t >> 5, l = t & 31;
    int qt = blockIdx.x, h = blockIdx.y, b = blockIdx.z;
    int q0 = qt * 64;
    size_t hbase = (size_t)(b * 16 + h) * 2048;

#pragma unroll
    for (int rep = 0; rep < 8; rep++) {
        int idx = t + rep * 128;
        int row = idx >> 4, c4 = idx & 15;
        float4 v = *(const float4*)&Q[(hbase + q0 + row) * 64 + c4 * 4];
        uint32_t h0 = CVT2(v.x, v.y), h1 = CVT2(v.z, v.w);
        float2 f0 = __bfloat1622float2(*(__nv_bfloat162*)&h0);
        float2 f1 = __bfloat1622float2(*(__nv_bfloat162*)&h1);
        uint32_t l0 = CVT2(v.x - f0.x, v.y - f0.y);
        uint32_t l1 = CVT2(v.z - f1.x, v.w - f1.y);
        int seg = c4 >> 1;
        uint32_t sw = row * 128 + ((seg ^ (row & 7)) << 4) + (c4 & 1) * 8;
        *(uint2*)(KH + sw) = make_uint2(h0, h1);
        *(uint2*)(KL + sw) = make_uint2(l0, l1);
    }
    __syncthreads();

    uint32_t qh[4][4], ql[4][4];
    {
        int qrow = w * 16 + (l & 7) + ((l >> 3) & 1) * 8;
#pragma unroll
        for (int ks = 0; ks < 4; ks++) {
            int seg = ks * 2 + (l >> 4);
            uint32_t off = qrow * 128 + ((seg ^ (qrow & 7)) << 4);
            LDSM4(qh[ks], sKH + off);
            LDSM4(ql[ks], sKL + off);
        }
    }

    int gqA = q0 + w * 16 + (l >> 2);

    for (int ph = 0; ph < 3; ph++) {
        float acc[8][4] = {};
        float mA = -1e30f, mB = -1e30f, lA = 0.f, lB = 0.f;
        int c_lo, c_hi;
        if (ph == 0) { c_lo = qt < 2 ? 2 - qt : 0; c_hi = 33 - qt; if (c_hi > 4) c_hi = 4; }
        else { c_lo = 0; c_hi = (ph == 1) ? 0 : 3; }
        int ntiles = (ph == 1) ? 4 : 8;
        int nt2max = ntiles >> 1;
        const float* Ksrc = (ph == 2) ? MEMV : K;
        const float* Vsrc = (ph == 2) ? MEMV : V;

        for (int c = c_lo; c <= c_hi; c++) {
            int key0 = (ph == 0) ? q0 - 128 + c * 64 : c * 64;
            bool needmask = (ph == 0) && (c != 2);
            __syncthreads();
#pragma unroll
            for (int rep = 0; rep < 8; rep++) {
                int idx = t + rep * 128;
                int row = idx >> 4, c4 = idx & 15;
                bool valid = (ph != 1) || (row < 32);
                size_t rowoff;
                if (ph == 2) rowoff = ((size_t)b * 256 + key0 + row) * 64;
                else if (ph == 1) rowoff = (hbase + (valid ? row * 64 : 0)) * 64;
                else rowoff = (hbase + key0 + row) * 64;
                float4 kv = valid ? *(const float4*)&Ksrc[rowoff + c4 * 4] : make_float4(0, 0, 0, 0);
                float4 vv = valid ? *(const float4*)&Vsrc[rowoff + c4 * 4] : make_float4(0, 0, 0, 0);
                uint32_t kh0 = CVT2(kv.x, kv.y), kh1 = CVT2(kv.z, kv.w);
                float2 kf0 = __bfloat1622float2(*(__nv_bfloat162*)&kh0);
                float2 kf1 = __bfloat1622float2(*(__nv_bfloat162*)&kh1);
                uint32_t kl0 = CVT2(kv.x - kf0.x, kv.y - kf0.y);
                uint32_t kl1 = CVT2(kv.z - kf1.x, kv.w - kf1.y);
                uint32_t vh0 = CVT2(vv.x, vv.y), vh1 = CVT2(vv.z, vv.w);
                float2 vf0 = __bfloat1622float2(*(__nv_bfloat162*)&vh0);
                float2 vf1 = __bfloat1622float2(*(__nv_bfloat162*)&vh1);
                uint32_t vl0 = CVT2(vv.x - vf0.x, vv.y - vf0.y);
                uint32_t vl1 = CVT2(vv.z - vf1.x, vv.w - vf1.y);
                int seg = c4 >> 1;
                uint32_t sw = row * 128 + ((seg ^ (row & 7)) << 4) + (c4 & 1) * 8;
                *(uint2*)(KH + sw) = make_uint2(kh0, kh1);
                *(uint2*)(KL + sw) = make_uint2(kl0, kl1);
                *(uint2*)(VH + sw) = make_uint2(vh0, vh1);
                *(uint2*)(VL + sw) = make_uint2(vl0, vl1);
            }
            __syncthreads();

            float sc[8][4] = {};
            for (int nt2 = 0; nt2 < nt2max; nt2++) {
                int krow = nt2 * 16 + (l & 7) + ((l >> 3) & 1) * 8;
#pragma unroll
                for (int ks = 0; ks < 4; ks++) {
                    int seg = ks * 2 + (l >> 4);
                    uint32_t off = krow * 128 + ((seg ^ (krow & 7)) << 4);
                    uint32_t bh[4], bl[4];
                    LDSM4(bh, sKH + off);
                    LDSM4(bl, sKL + off);
                    MMA_BF16(sc[2 * nt2], qh[ks], bh[0], bh[2]);
                    MMA_BF16(sc[2 * nt2], qh[ks], bl[0], bl[2]);
                    MMA_BF16(sc[2 * nt2], ql[ks], bh[0], bh[2]);
                    MMA_BF16(sc[2 * nt2 + 1], qh[ks], bh[1], bh[3]);
                    MMA_BF16(sc[2 * nt2 + 1], qh[ks], bl[1], bl[3]);
                    MMA_BF16(sc[2 * nt2 + 1], ql[ks], bh[1], bh[3]);
                }
            }

            for (int j = 0; j < ntiles; j++) {
                int gk = key0 + j * 8 + 2 * (l & 3);
                if (needmask) {
                    int dA0 = gqA - gk;     if (dA0 < 0) dA0 = -dA0;
                    int dA1 = gqA - gk - 1; if (dA1 < 0) dA1 = -dA1;
                    int dB0 = gqA + 8 - gk;     if (dB0 < 0) dB0 = -dB0;
                    int dB1 = gqA + 8 - gk - 1; if (dB1 < 0) dB1 = -dB1;
                    sc[j][0] = (dA0 <= WINR) ? sc[j][0] * ASCALE : -1e30f;
                    sc[j][1] = (dA1 <= WINR) ? sc[j][1] * ASCALE : -1e30f;
                    sc[j][2] = (dB0 <= WINR) ? sc[j][2] * ASCALE : -1e30f;
                    sc[j][3] = (dB1 <= WINR) ? sc[j][3] * ASCALE : -1e30f;
                } else if (ph == 1) {
                    bool ok = (j * 8 + 2 * (l & 3)) < 32;
                    sc[j][0] = ok ? sc[j][0] * ASCALE : -1e30f;
                    sc[j][1] = ok ? sc[j][1] * ASCALE : -1e30f;
                    sc[j][2] = ok ? sc[j][2] * ASCALE : -1e30f;
                    sc[j][3] = ok ? sc[j][3] * ASCALE : -1e30f;
                } else {
                    sc[j][0] *= ASCALE; sc[j][1] *= ASCALE;
                    sc[j][2] *= ASCALE; sc[j][3] *= ASCALE;
                }
            }

            float mxA = -1e30f, mxB = -1e30f;
            for (int j = 0; j < ntiles; j++) {
                mxA = fmaxf(mxA, fmaxf(sc[j][0], sc[j][1]));
                mxB = fmaxf(mxB, fmaxf(sc[j][2], sc[j][3]));
            }
            mxA = fmaxf(mxA, __shfl_xor_sync(0xffffffffu, mxA, 1));
            mxA = fmaxf(mxA, __shfl_xor_sync(0xffffffffu, mxA, 2));
            mxB = fmaxf(mxB, __shfl_xor_sync(0xffffffffu, mxB, 1));
            mxB = fmaxf(mxB, __shfl_xor_sync(0xffffffffu, mxB, 2));
            float nmA = fmaxf(mA, mxA), nmB = fmaxf(mB, mxB);
            float fA = __expf(mA - nmA), fB = __expf(mB - nmB);
            mA = nmA; mB = nmB;
            float sA = 0.f, sB = 0.f;
            for (int j = 0; j < ntiles; j++) {
                sc[j][0] = __expf(sc[j][0] - nmA);
                sc[j][1] = __expf(sc[j][1] - nmA);
                sc[j][2] = __expf(sc[j][2] - nmB);
                sc[j][3] = __expf(sc[j][3] - nmB);
                sA += sc[j][0] + sc[j][1];
                sB += sc[j][2] + sc[j][3];
            }
            sA += __shfl_xor_sync(0xffffffffu, sA, 1);
            sA += __shfl_xor_sync(0xffffffffu, sA, 2);
            sB += __shfl_xor_sync(0xffffffffu, sB, 1);
            sB += __shfl_xor_sync(0xffffffffu, sB, 2);
            lA = lA * fA + sA;
            lB = lB * fB + sB;
#pragma unroll
            for (int j = 0; j < 8; j++) {
                acc[j][0] *= fA; acc[j][1] *= fA;
                acc[j][2] *= fB; acc[j][3] *= fB;
            }

            for (int kt = 0; kt < nt2max; kt++) {
                uint32_t ah[4], al_[4];
                ah[0] = CVT2(sc[2 * kt][0], sc[2 * kt][1]);
                ah[1] = CVT2(sc[2 * kt][2], sc[2 * kt][3]);
                ah[2] = CVT2(sc[2 * kt + 1][0], sc[2 * kt + 1][1]);
                ah[3] = CVT2(sc[2 * kt + 1][2], sc[2 * kt + 1][3]);
                {
                    float2 r0 = __bfloat1622float2(*(__nv_bfloat162*)&ah[0]);
                    float2 r1 = __bfloat1622float2(*(__nv_bfloat162*)&ah[1]);
                    float2 r2 = __bfloat1622float2(*(__nv_bfloat162*)&ah[2]);
                    float2 r3 = __bfloat1622float2(*(__nv_bfloat162*)&ah[3]);
                    al_[0] = CVT2(sc[2 * kt][0] - r0.x, sc[2 * kt][1] - r0.y);
                    al_[1] = CVT2(sc[2 * kt][2] - r1.x, sc[2 * kt][3] - r1.y);
                    al_[2] = CVT2(sc[2 * kt + 1][0] - r2.x, sc[2 * kt + 1][1] - r2.y);
                    al_[3] = CVT2(sc[2 * kt + 1][2] - r3.x, sc[2 * kt + 1][3] - r3.y);
                }
                int vrow = kt * 16 + (l & 7) + ((l >> 3) & 1) * 8;
#pragma unroll
                for (int jn2 = 0; jn2 < 4; jn2++) {
                    int seg = jn2 * 2 + (l >> 4);
                    uint32_t off = vrow * 128 + ((seg ^ (vrow & 7)) << 4);
                    uint32_t bh[4], bl[4];
                    LDSM4T(bh, sVH + off);
                    LDSM4T(bl, sVL + off);
                    MMA_BF16(acc[2 * jn2], ah, bh[0], bh[1]);
                    MMA_BF16(acc[2 * jn2], ah, bl[0], bl[1]);
                    MMA_BF16(acc[2 * jn2], al_, bh[0], bh[1]);
                    MMA_BF16(acc[2 * jn2 + 1], ah, bh[2], bh[3]);
                    MMA_BF16(acc[2 * jn2 + 1], ah, bl[2], bl[3]);
                    MMA_BF16(acc[2 * jn2 + 1], al_, bh[2], bh[3]);
                }
            }
        }

        float invA = 1.f / lA, invB = 1.f / lB;
#pragma unroll
        for (int j = 0; j < 8; j++) {
            int hd = j * 8 + 2 * (l & 3);
            size_t offA = (hbase + gqA) * 64 + hd;
            size_t offB = offA + 8 * 64;
            float2 oA = make_float2(acc[j][0] * invA, acc[j][1] * invA);
            float2 oB = make_float2(acc[j][2] * invB, acc[j][3] * invB);
            if (ph > 0) {
                float2 pA = *(float2*)&O[offA]; oA.x += pA.x; oA.y += pA.y;
                float2 pB = *(float2*)&O[offB]; oB.x += pB.x; oB.y += pB.y;
            }
            *(float2*)&O[offA] = oA;
            *(float2*)&O[offB] = oB;
        }
    }
}

// ---------------------------------------------------------------------------
// convert out_W -> bf16 hi/lo (W only; A is fused into k_outproj loader).
// ---------------------------------------------------------------------------
__global__ __launch_bounds__(256) void k_cvt_w(const float* __restrict__ W,
                                               __nv_bfloat16* __restrict__ Wh,
                                               __nv_bfloat16* __restrict__ Wl) {
    int idx = blockIdx.x * 256 + threadIdx.x;     // over 256K float4
    float4 v = *(const float4*)&W[(size_t)idx * 4];
    __nv_bfloat162 h0 = __floats2bfloat162_rn(v.x, v.y);
    __nv_bfloat162 h1 = __floats2bfloat162_rn(v.z, v.w);
    __nv_bfloat162 l0 = __floats2bfloat162_rn(v.x - __bfloat162float(h0.x),
                                              v.y - __bfloat162float(h0.y));
    __nv_bfloat162 l1 = __floats2bfloat162_rn(v.z - __bfloat162float(h1.x),
                                              v.w - __bfloat162float(h1.y));
    size_t dst = (size_t)idx * 4;
    *(uint32_t*)&Wh[dst]     = *(uint32_t*)&h0;
    *(uint32_t*)&Wh[dst + 2] = *(uint32_t*)&h1;
    *(uint32_t*)&Wl[dst]     = *(uint32_t*)&l0;
    *(uint32_t*)&Wl[dst + 2] = *(uint32_t*)&l1;
}

// ---------------------------------------------------------------------------
// out = fused(C) @ W^T + b via mma.sync bf16x3. Kc=32, 2-stage pipeline.
// A side: LDG fp32 gather from g_comb + in-register bf16 hi/lo split + STS
// (conversion fused, no g_ah/g_al pass). W side: cp.async (verified).
// smem: stage s at s*40960; planes AH+0, AL+10240, WH+20480, WL+30720.
// ---------------------------------------------------------------------------
#define OP_LDG_A(kc)                                                           \
    do {                                                                       \
        int _hh = (kc) >> 1;                                                   \
        int _hdb = ((kc) & 1) * 32;                                            \
        _Pragma("unroll")                                                      \
        for (int rep = 0; rep < 2; rep++) {                                    \
            int idx = t + rep * 256;                                           \
            int row = idx >> 2, seg = idx & 3;                                 \
            int m = m0 + row;                                                  \
            int bi = m >> 11, ni = m & 2047;                                   \
            const float* s = &C[((size_t)(bi * 16 + _hh) * 2048 + ni) * 64     \
                                + _hdb + seg * 8];                             \
            av[rep][0] = *(const float4*)s;                                    \
            av[rep][1] = *(const float4*)(s + 4);                              \
        }                                                                      \
    } while (0)

#define OP_STS_A(s)                                                            \
    do {                                                                       \
        _Pragma("unroll")                                                      \
        for (int rep = 0; rep < 2; rep++) {                                    \
            int idx = t + rep * 256;                                           \
            int row = idx >> 2, seg = idx & 3;                                 \
            uint32_t h0 = CVT2(av[rep][0].x, av[rep][0].y);                    \
            uint32_t h1 = CVT2(av[rep][0].z, av[rep][0].w);                    \
            uint32_t h2 = CVT2(av[rep][1].x, av[rep][1].y);                    \
            uint32_t h3 = CVT2(av[rep][1].z, av[rep][1].w);                    \
            float2 f0 = __bfloat1622float2(*(__nv_bfloat162*)&h0);             \
            float2 f1 = __bfloat1622float2(*(__nv_bfloat162*)&h1);             \
            float2 f2 = __bfloat1622float2(*(__nv_bfloat162*)&h2);             \
            float2 f3 = __bfloat1622float2(*(__nv_bfloat162*)&h3);             \
            uint32_t l0 = CVT2(av[rep][0].x - f0.x, av[rep][0].y - f0.y);      \
            uint32_t l1 = CVT2(av[rep][0].z - f1.x, av[rep][0].w - f1.y);      \
            uint32_t l2 = CVT2(av[rep][1].x - f2.x, av[rep][1].y - f2.y);      \
            uint32_t l3 = CVT2(av[rep][1].z - f3.x, av[rep][1].w - f3.y);      \
            uint32_t off = (s) * 40960 + row * 80 + seg * 16;                  \
            *(uint4*)(smc + off)         = make_uint4(h0, h1, h2, h3);         \
            *(uint4*)(smc + 10240 + off) = make_uint4(l0, l1, l2, l3);         \
        }                                                                      \
    } while (0)

#define OP_LOAD_W(kc, s)                                                       \
    do {                                                                       \
        uint32_t _base = sb + (s) * 40960 + 20480;                             \
        _Pragma("unroll")                                                      \
        for (int rep = 0; rep < 4; rep++) {                                    \
            int idx = t + rep * 256;                                           \
            int plane = idx >> 9;                                              \
            int rem = idx & 511;                                               \
            int row = rem >> 2, seg = rem & 3;                                 \
            uint32_t dst = _base + plane * 10240 + row * 80 + seg * 16;        \
            const __nv_bfloat16* src = plane ? Wlg : Whg;                      \
            CP_ASYNC16(dst, &src[(size_t)(n0 + row) * 1024 + (kc) * 32 + seg * 8]); \
        }                                                                      \
    } while (0)

__global__ __launch_bounds__(256, 2) void k_outproj_mma(const float* __restrict__ C,
                                                        const __nv_bfloat16* __restrict__ Whg,
                                                        const __nv_bfloat16* __restrict__ Wlg,
                                                        const float* __restrict__ bias,
                                                        float* __restrict__ out) {
    extern __shared__ char smc[];
    uint32_t sb = smem_u32(smc);
    int t = threadIdx.x;
    int wid = t >> 5, l = t & 31;
    int wm = wid & 3, wn = wid >> 2;
    int m0 = blockIdx.x * 128, n0 = blockIdx.y * 128;

    float acc[2][8][4] = {};
    float4 av[2][2];

    int row_a = wm * 32 + (l & 15);
    int sega  = (l >> 4);
    int row_b = wn * 64 + ((l >> 4) & 1) * 8 + (l & 7);
    int segb  = ((l >> 3) & 1);

    OP_LDG_A(0);
    OP_LOAD_W(0, 0);
    CP_COMMIT();

    for (int kc = 0; kc < 32; kc++) {
        OP_STS_A(kc & 1);
        if (kc + 1 < 32) {
            OP_LOAD_W(kc + 1, (kc + 1) & 1);
            CP_COMMIT();
            OP_LDG_A(kc + 1);
            CP_WAIT(1);
        } else {
            CP_WAIT(0);
        }
        __syncthreads();
        uint32_t base = sb + (kc & 1) * 40960;

#pragma unroll
        for (int ks = 0; ks < 2; ks++) {
            uint32_t ah[2][4], al_[2][4];
#pragma unroll
            for (int mt = 0; mt < 2; mt++) {
                int ra = row_a + mt * 16;
                uint32_t off = ra * 80 + (ks * 2 + sega) * 16;
                LDSM4(ah[mt], base + off);
                LDSM4(al_[mt], base + 10240 + off);
            }
#pragma unroll
            for (int ntp = 0; ntp < 4; ntp++) {
                int rb = row_b + ntp * 16;
                uint32_t off = rb * 80 + (ks * 2 + segb) * 16;
                uint32_t bh[4], bl[4];
                LDSM4(bh, base + 20480 + off);
                LDSM4(bl, base + 30720 + off);
#pragma unroll
                for (int mt = 0; mt < 2; mt++) {
#pragma unroll
                    for (int half = 0; half < 2; half++) {
                        float* d = acc[mt][ntp * 2 + half];
                        MMA_BF16(d, ah[mt], bh[half * 2], bh[half * 2 + 1]);
                        MMA_BF16(d, ah[mt], bl[half * 2], bl[half * 2 + 1]);
                        MMA_BF16(d, al_[mt], bh[half * 2], bh[half * 2 + 1]);
                    }
                }
            }
        }
        __syncthreads();
    }

#pragma unroll
    for (int mt = 0; mt < 2; mt++) {
        int r0 = m0 + wm * 32 + mt * 16 + (l >> 2);
#pragma unroll
        for (int nt = 0; nt < 8; nt++) {
            int c = n0 + wn * 64 + nt * 8 + 2 * (l & 3);
            float b0 = bias[c], b1 = bias[c + 1];
            float* d = acc[mt][nt];
            *(float2*)&out[(size_t)r0 * 1024 + c] = make_float2(d[0] + b0, d[1] + b1);
            *(float2*)&out[(size_t)(r0 + 8) * 1024 + c] = make_float2(d[2] + b0, d[3] + b1);
        }
    }
}

// ---------------------------------------------------------------------------
__global__ __launch_bounds__(128) void k_heads(const float* __restrict__ C,
                                               const float* __restrict__ tW, const float* __restrict__ tb,
                                               const float* __restrict__ iW, const float* __restrict__ ib,
                                               const float* __restrict__ cW, const float* __restrict__ cb,
                                               float* __restrict__ out) {
    int r = blockIdx.x;
    int b = r >> 11, n = r & 2047;
    __shared__ float last[64];
    int t = threadIdx.x;
    if (t < 64) last[t] = C[((size_t)(b * 16) * 2048 + n) * 64 + t];
    __syncthreads();
    if (t < 2) {
        float s = tb[t];
        for (int k = 0; k < 64; k++) s += last[k] * tW[t * 64 + k];
        out[4194304 + (size_t)r * 2 + t] = s;
    } else if (t < 66) {
        int j = t - 2;
        float s = ib[j];
        for (int k = 0; k < 64; k++) s += last[k] * iW[j * 64 + k];
        out[4202496 + (size_t)r * 64 + j] = s;
    } else if (t < 98) {
        int j = t - 66;
        float s = cb[j];
        for (int k = 0; k < 64; k++) s += last[k] * cW[j * 64 + k];
        out[4464640 + (size_t)r * 32 + j] = s;
    }
}

// ---------------------------------------------------------------------------
extern "C" void kernel_launch(void* const* d_in, const int* in_sizes, int n_in,
                              void* d_out, int out_size) {
    const float* x   = (const float*)d_in[0];
    const float* mem = (const float*)d_in[1];
    P3 Us  = { (const float*)d_in[2],  (const float*)d_in[8],  (const float*)d_in[14] };
    P3 Vs  = { (const float*)d_in[3],  (const float*)d_in[9],  (const float*)d_in[15] };
    P3 als = { (const float*)d_in[4],  (const float*)d_in[10], (const float*)d_in[16] };
    P3 As  = { (const float*)d_in[5],  (const float*)d_in[11], (const float*)d_in[17] };
    P3 Bls = { (const float*)d_in[6],  (const float*)d_in[12], (const float*)d_in[18] };
    P3 bis = { (const float*)d_in[7],  (const float*)d_in[13], (const float*)d_in[19] };
    const float* outW = (const float*)d_in[20];
    const float* outb = (const float*)d_in[21];
    const float* tW = (const float*)d_in[22];
    const float* tb = (const float*)d_in[23];
    const float* iW = (const float*)d_in[24];
    const float* ib = (const float*)d_in[25];
    const float* cW = (const float*)d_in[26];
    const float* cb = (const float*)d_in[27];
    float* out = (float*)d_out;

    void *pT, *pL, *pQKV, *pC, *pWh, *pWl;
    cudaGetSymbolAddress(&pT, g_t);
    cudaGetSymbolAddress(&pL, g_l);
    cudaGetSymbolAddress(&pQKV, g_qkv);
    cudaGetSymbolAddress(&pC, g_comb);
    cudaGetSymbolAddress(&pWh, g_wh);
    cudaGetSymbolAddress(&pWl, g_wl);
    float* Tb = (float*)pT;
    float* Lb = (float*)pL;
    float* QKV = (float*)pQKV;
    float* Cb = (float*)pC;
    const size_t QSZ = (size_t)BATCH * NHEAD * NSEQ * 64;

    k_xu<<<dim3(64, 3), 128>>>(x, Us, als, Tb);
    k_lora<<<4096, 128>>>(x, As, Lb);
    k_proj<<<dim3(32, 8, 3), 256>>>(Tb, Lb, Vs, Bls, bis, QKV);
    k_cvt_w<<<1024, 256>>>(outW, (__nv_bfloat16*)pWh, (__nv_bfloat16*)pWl);

    const int SMEM_ATTN = 32768;
    cudaFuncSetAttribute(k_attn_mma, cudaFuncAttributeMaxDynamicSharedMemorySize, SMEM_ATTN);
    k_attn_mma<<<dim3(32, 16, 2), 128, SMEM_ATTN>>>(QKV, QKV + QSZ, QKV + 2 * QSZ, mem, Cb);

    const int SMEM_OP = 81920;
    cudaFuncSetAttribute(k_outproj_mma, cudaFuncAttributeMaxDynamicSharedMemorySize, SMEM_OP);
    k_outproj_mma<<<dim3(32, 8), 256, SMEM_OP>>>(Cb,
                                                 (const __nv_bfloat16*)pWh,
                                                 (const __nv_bfloat16*)pWl,
                                                 outb, out);

    k_heads<<<4096, 128>>>(Cb, tW, tb, iW, ib, cW, cb, out);
}

// round 15
// speedup vs baseline: 1.0581x; 1.0581x over previous
#include <cuda_runtime.h>
#include <cuda_bf16.h>
#include <math.h>
#include <stdint.h>

#define NSEQ 2048
#define BATCH 2
#define NHEAD 16
#define MROWS 4096
#define WINR 128
#define ASCALE 0.125f

typedef unsigned long long u64;
struct P3 { const float* a; const float* b; const float* c; };
__device__ __forceinline__ const float* sel(P3 p, int i) {
    return i == 0 ? p.a : (i == 1 ? p.b : p.c);
}

__device__ __forceinline__ u64 PK2(float lo, float hi) {
    u64 r; asm("mov.b64 %0,{%1,%2};" : "=l"(r) : "f"(lo), "f"(hi)); return r;
}
__device__ __forceinline__ u64 DUP(float v) { return PK2(v, v); }
__device__ __forceinline__ void FMA2(u64& d, u64 a, u64 b) {
    asm("fma.rn.f32x2 %0,%1,%2,%0;" : "+l"(d) : "l"(a), "l"(b));
}
__device__ __forceinline__ float2 UPK(u64 v) {
    float2 f; asm("mov.b64 {%0,%1},%2;" : "=f"(f.x), "=f"(f.y) : "l"(v)); return f;
}

__device__ __forceinline__ uint32_t smem_u32(const void* p) {
    uint32_t a;
    asm("{ .reg .u64 t; cvta.to.shared.u64 t, %1; cvt.u32.u64 %0, t; }" : "=r"(a) : "l"(p));
    return a;
}

// ---- portable tensor-core + async-copy ops (sm_80+ baseline PTX) ----
__device__ __forceinline__ void MMA_BF16(float* d, const uint32_t* a, uint32_t b0, uint32_t b1) {
    asm volatile(
        "mma.sync.aligned.m16n8k16.row.col.f32.bf16.bf16.f32 "
        "{%0,%1,%2,%3}, {%4,%5,%6,%7}, {%8,%9}, {%0,%1,%2,%3};"
        : "+f"(d[0]), "+f"(d[1]), "+f"(d[2]), "+f"(d[3])
        : "r"(a[0]), "r"(a[1]), "r"(a[2]), "r"(a[3]), "r"(b0), "r"(b1));
}
__device__ __forceinline__ void LDSM4(uint32_t* r, uint32_t addr) {
    asm volatile("ldmatrix.sync.aligned.m8n8.x4.shared.b16 {%0,%1,%2,%3}, [%4];"
                 : "=r"(r[0]), "=r"(r[1]), "=r"(r[2]), "=r"(r[3]) : "r"(addr));
}
__device__ __forceinline__ void LDSM4T(uint32_t* r, uint32_t addr) {
    asm volatile("ldmatrix.sync.aligned.m8n8.x4.trans.shared.b16 {%0,%1,%2,%3}, [%4];"
                 : "=r"(r[0]), "=r"(r[1]), "=r"(r[2]), "=r"(r[3]) : "r"(addr));
}
__device__ __forceinline__ uint32_t CVT2(float lo, float hi) {
    uint32_t r; asm("cvt.rn.bf16x2.f32 %0, %1, %2;" : "=r"(r) : "f"(hi), "f"(lo)); return r;
}
#define CP_ASYNC16(dst, src) \
    asm volatile("cp.async.ca.shared.global [%0], [%1], 16;" :: "r"(dst), "l"(src) : "memory")
#define CP_COMMIT() asm volatile("cp.async.commit_group;" ::: "memory")
#define CP_WAIT(n)  asm volatile("cp.async.wait_group %0;" :: "n"(n) : "memory")

// ---------------- scratch ----------------
__device__ float g_l[3 * MROWS * 4];
__device__ float g_qkv[3 * BATCH * NHEAD * NSEQ * 64];
__device__ float g_comb[BATCH * NHEAD * NSEQ * 64];
__device__ __nv_bfloat16 g_th[3 * MROWS * 64];
__device__ __nv_bfloat16 g_tl[3 * MROWS * 64];
__device__ __nv_bfloat16 g_vh[3 * 1024 * 64];
__device__ __nv_bfloat16 g_vl[3 * 1024 * 64];
__device__ __nv_bfloat16 g_wh[1024 * 1024];
__device__ __nv_bfloat16 g_wl[1024 * 1024];

// ---------------------------------------------------------------------------
// t = x @ U * alpha -> bf16 hi/lo planes.  64x64 tile, 128 thr, 8x4 micro.
// ---------------------------------------------------------------------------
__global__ __launch_bounds__(128) void k_xu(const float* __restrict__ X,
                                            P3 Us, P3 als,
                                            __nv_bfloat16* __restrict__ TH,
                                            __nv_bfloat16* __restrict__ TL) {
    __shared__ float a_s[64][68];
    __shared__ float b_s[64][68];
    int p = blockIdx.y;
    const float* U = sel(Us, p);
    const float* alpha = sel(als, p);
    __nv_bfloat16* Th = TH + (size_t)p * MROWS * 64;
    __nv_bfloat16* Tl = TL + (size_t)p * MROWS * 64;
    int t = threadIdx.x;
    int m0 = blockIdx.x * 64;
    int tm = t >> 4, tn4 = t & 15;
    u64 acc2[8][2] = {};
    for (int k0 = 0; k0 < 1024; k0 += 64) {
#pragma unroll
        for (int rep = 0; rep < 8; rep++) {
            int fidx = t + rep * 128;
            int m = fidx >> 4, kq = fidx & 15;
            float4 v = *(const float4*)&X[(size_t)(m0 + m) * 1024 + k0 + kq * 4];
            a_s[kq * 4 + 0][m] = v.x; a_s[kq * 4 + 1][m] = v.y;
            a_s[kq * 4 + 2][m] = v.z; a_s[kq * 4 + 3][m] = v.w;
        }
#pragma unroll
        for (int rep = 0; rep < 8; rep++) {
            int fidx = t + rep * 128;
            int kk = fidx >> 4, nq = fidx & 15;
            *(float4*)&b_s[kk][nq * 4] = *(const float4*)&U[(size_t)(k0 + kk) * 64 + nq * 4];
        }
        __syncthreads();
#pragma unroll 8
        for (int kk = 0; kk < 64; kk++) {
            float4 a0 = *(const float4*)&a_s[kk][tm * 8];
            float4 a1 = *(const float4*)&a_s[kk][tm * 8 + 4];
            ulonglong2 bp = *(const ulonglong2*)&b_s[kk][tn4 * 4];
            float aa[8] = {a0.x, a0.y, a0.z, a0.w, a1.x, a1.y, a1.z, a1.w};
#pragma unroll
            for (int i = 0; i < 8; i++) {
                u64 d = DUP(aa[i]);
                FMA2(acc2[i][0], d, bp.x);
                FMA2(acc2[i][1], d, bp.y);
            }
        }
        __syncthreads();
    }
    float al0 = alpha[tn4 * 4 + 0], al1 = alpha[tn4 * 4 + 1];
    float al2 = alpha[tn4 * 4 + 2], al3 = alpha[tn4 * 4 + 3];
#pragma unroll
    for (int i = 0; i < 8; i++) {
        float2 c0 = UPK(acc2[i][0]), c1 = UPK(acc2[i][1]);
        float v0 = c0.x * al0, v1 = c0.y * al1, v2 = c1.x * al2, v3 = c1.y * al3;
        uint32_t h0 = CVT2(v0, v1), h1 = CVT2(v2, v3);
        float2 f0 = __bfloat1622float2(*(__nv_bfloat162*)&h0);
        float2 f1 = __bfloat1622float2(*(__nv_bfloat162*)&h1);
        uint32_t l0 = CVT2(v0 - f0.x, v1 - f0.y);
        uint32_t l1 = CVT2(v2 - f1.x, v3 - f1.y);
        size_t off = (size_t)(m0 + tm * 8 + i) * 64 + tn4 * 4;
        *(uint2*)&Th[off] = make_uint2(h0, h1);
        *(uint2*)&Tl[off] = make_uint2(l0, l1);
    }
}

// ---------------------------------------------------------------------------
// l = x @ A (12 cols fused).
// ---------------------------------------------------------------------------
__global__ __launch_bounds__(128) void k_lora(const float* __restrict__ X,
                                              P3 As, float* __restrict__ Lb) {
    int m = blockIdx.x;
    int t = threadIdx.x;
    float p[12] = {};
    const float* A0 = As.a; const float* A1 = As.b; const float* A2 = As.c;
    for (int k = t; k < 1024; k += 128) {
        float xv = X[(size_t)m * 1024 + k];
#pragma unroll
        for (int j = 0; j < 4; j++) {
            p[j]     += xv * A0[k * 4 + j];
            p[4 + j] += xv * A1[k * 4 + j];
            p[8 + j] += xv * A2[k * 4 + j];
        }
    }
    __shared__ float red[12][128];
#pragma unroll
    for (int j = 0; j < 12; j++) red[j][t] = p[j];
    __syncthreads();
    for (int s = 64; s > 0; s >>= 1) {
        if (t < s) {
#pragma unroll
            for (int j = 0; j < 12; j++) red[j][t] += red[j][t + s];
        }
        __syncthreads();
    }
    if (t < 12) {
        int pr = t >> 2, j = t & 3;
        Lb[(size_t)pr * MROWS * 4 + (size_t)m * 4 + j] = red[t][0];
    }
}

// ---------------------------------------------------------------------------
// proj via mma.sync bf16x3: out = T @ V^T (K=64) + l@B (fp32 epi) + bias.
// 128x128 tile, 256 thr, single K chunk. smem planes TH/TL/VH/VL 144B-stride.
// grid (32, 8, 3).
// ---------------------------------------------------------------------------
__global__ __launch_bounds__(256, 2) void k_proj_mma(const __nv_bfloat16* __restrict__ THg,
                                                     const __nv_bfloat16* __restrict__ TLg,
                                                     const __nv_bfloat16* __restrict__ VHg,
                                                     const __nv_bfloat16* __restrict__ VLg,
                                                     const float* __restrict__ Lb,
                                                     P3 Bls, P3 bis,
                                                     float* __restrict__ QKV) {
    extern __shared__ char smp[];
    uint32_t sb = smem_u32(smp);
    const int TH = 0, TL = 18432, VH = 36864, VL = 55296, BLS = 73728;
    float* blS = (float*)(smp + BLS);
    int p = blockIdx.z;
    const __nv_bfloat16* Tph = THg + (size_t)p * MROWS * 64;
    const __nv_bfloat16* Tpl = TLg + (size_t)p * MROWS * 64;
    const __nv_bfloat16* Vph = VHg + (size_t)p * 1024 * 64;
    const __nv_bfloat16* Vpl = VLg + (size_t)p * 1024 * 64;
    const float* L = Lb + (size_t)p * MROWS * 4;
    const float* Blora = sel(Bls, p);
    const float* bias = sel(bis, p);
    float* O = QKV + (size_t)p * BATCH * NHEAD * NSEQ * 64;

    int t = threadIdx.x;
    int wid = t >> 5, l = t & 31;
    int wm = wid & 3, wn = wid >> 2;
    int m0 = blockIdx.x * 128, n0 = blockIdx.y * 128;

    // ---- load 4 planes via cp.async (1024 segs each) ----
#pragma unroll
    for (int rep = 0; rep < 16; rep++) {
        int idx = t + rep * 256;
        int plane = idx >> 10;
        int rem = idx & 1023;
        int row = rem >> 3, seg = rem & 7;
        uint32_t dst = sb + plane * 18432 + row * 144 + seg * 16;
        const __nv_bfloat16* src;
        size_t g;
        if (plane == 0)      { src = Tph; g = (size_t)(m0 + row) * 64; }
        else if (plane == 1) { src = Tpl; g = (size_t)(m0 + row) * 64; }
        else if (plane == 2) { src = Vph; g = (size_t)(n0 + row) * 64; }
        else                 { src = Vpl; g = (size_t)(n0 + row) * 64; }
        CP_ASYNC16(dst, &src[g + seg * 8]);
    }
    if (t < 128) {
#pragma unroll
        for (int j = 0; j < 4; j++)
            blS[j * 128 + t] = Blora[(size_t)j * 1024 + n0 + t];
    }
    CP_COMMIT();
    CP_WAIT(0);
    __syncthreads();

    float acc[2][8][4] = {};
    int row_a = wm * 32 + (l & 15);
    int sega  = (l >> 4);
    int row_b = wn * 64 + ((l >> 4) & 1) * 8 + (l & 7);
    int segb  = ((l >> 3) & 1);

#pragma unroll
    for (int ks = 0; ks < 4; ks++) {
        uint32_t ah[2][4], al_[2][4];
#pragma unroll
        for (int mt = 0; mt < 2; mt++) {
            int ra = row_a + mt * 16;
            uint32_t off = ra * 144 + (ks * 2 + sega) * 16;
            LDSM4(ah[mt], sb + TH + off);
            LDSM4(al_[mt], sb + TL + off);
        }
#pragma unroll
        for (int ntp = 0; ntp < 4; ntp++) {
            int rb = row_b + ntp * 16;
            uint32_t off = rb * 144 + (ks * 2 + segb) * 16;
            uint32_t bh[4], bl[4];
            LDSM4(bh, sb + VH + off);
            LDSM4(bl, sb + VL + off);
#pragma unroll
            for (int mt = 0; mt < 2; mt++) {
#pragma unroll
                for (int half = 0; half < 2; half++) {
                    float* d = acc[mt][ntp * 2 + half];
                    MMA_BF16(d, ah[mt], bh[half * 2], bh[half * 2 + 1]);
                    MMA_BF16(d, ah[mt], bl[half * 2], bl[half * 2 + 1]);
                    MMA_BF16(d, al_[mt], bh[half * 2], bh[half * 2 + 1]);
                }
            }
        }
    }

    // ---- epilogue: + lora + bias, scatter to [B,H,N,HD] ----
#pragma unroll
    for (int mt = 0; mt < 2; mt++) {
        int r0 = m0 + wm * 32 + mt * 16 + (l >> 2);
        int r1 = r0 + 8;
        float lv0[4], lv1[4];
#pragma unroll
        for (int j = 0; j < 4; j++) {
            lv0[j] = L[(size_t)r0 * 4 + j];
            lv1[j] = L[(size_t)r1 * 4 + j];
        }
#pragma unroll
        for (int nt = 0; nt < 8; nt++) {
            int c = n0 + wn * 64 + nt * 8 + 2 * (l & 3);
            int cl = c - n0;
            float b0 = bias[c], b1 = bias[c + 1];
            float l00 = 0.f, l01 = 0.f, l10 = 0.f, l11 = 0.f;
#pragma unroll
            for (int j = 0; j < 4; j++) {
                float B0 = blS[j * 128 + cl], B1 = blS[j * 128 + cl + 1];
                l00 += lv0[j] * B0; l01 += lv0[j] * B1;
                l10 += lv1[j] * B0; l11 += lv1[j] * B1;
            }
            float* d = acc[mt][nt];
            int h = c >> 6, hd = c & 63;
            size_t o0 = ((size_t)((r0 >> 11) * 16 + h) * 2048 + (r0 & 2047)) * 64 + hd;
            size_t o1 = ((size_t)((r1 >> 11) * 16 + h) * 2048 + (r1 & 2047)) * 64 + hd;
            *(float2*)&O[o0] = make_float2(d[0] + l00 + b0, d[1] + l01 + b1);
            *(float2*)&O[o1] = make_float2(d[2] + l10 + b0, d[3] + l11 + b1);
        }
    }
}

// ---------------------------------------------------------------------------
// fused 3-branch flash attention via mma.sync bf16x3 (R7/R10 verbatim).
// ---------------------------------------------------------------------------
__global__ __launch_bounds__(128) void k_attn_mma(const float* __restrict__ Q,
                                                  const float* __restrict__ K,
                                                  const float* __restrict__ V,
                                                  const float* __restrict__ MEMV,
                                                  float* __restrict__ O) {
    extern __shared__ char sma[];
    char* KH = sma;
    char* KL = sma + 8192;
    char* VH = sma + 16384;
    char* VL = sma + 24576;
    uint32_t sKH = smem_u32(KH), sKL = smem_u32(KL);
    uint32_t sVH = smem_u32(VH), sVL = smem_u32(VL);

    int t = threadIdx.x;
    int w = t >> 5, l = t & 31;
    int qt = blockIdx.x, h = blockIdx.y, b = blockIdx.z;
    int q0 = qt * 64;
    size_t hbase = (size_t)(b * 16 + h) * 2048;

#pragma unroll
    for (int rep = 0; rep < 8; rep++) {
        int idx = t + rep * 128;
        int row = idx >> 4, c4 = idx & 15;
        float4 v = *(const float4*)&Q[(hbase + q0 + row) * 64 + c4 * 4];
        uint32_t h0 = CVT2(v.x, v.y), h1 = CVT2(v.z, v.w);
        float2 f0 = __bfloat1622float2(*(__nv_bfloat162*)&h0);
        float2 f1 = __bfloat1622float2(*(__nv_bfloat162*)&h1);
        uint32_t l0 = CVT2(v.x - f0.x, v.y - f0.y);
        uint32_t l1 = CVT2(v.z - f1.x, v.w - f1.y);
        int seg = c4 >> 1;
        uint32_t sw = row * 128 + ((seg ^ (row & 7)) << 4) + (c4 & 1) * 8;
        *(uint2*)(KH + sw) = make_uint2(h0, h1);
        *(uint2*)(KL + sw) = make_uint2(l0, l1);
    }
    __syncthreads();

    uint32_t qh[4][4], ql[4][4];
    {
        int qrow = w * 16 + (l & 7) + ((l >> 3) & 1) * 8;
#pragma unroll
        for (int ks = 0; ks < 4; ks++) {
            int seg = ks * 2 + (l >> 4);
            uint32_t off = qrow * 128 + ((seg ^ (qrow & 7)) << 4);
            LDSM4(qh[ks], sKH + off);
            LDSM4(ql[ks], sKL + off);
        }
    }

    int gqA = q0 + w * 16 + (l >> 2);

    for (int ph = 0; ph < 3; ph++) {
        float acc[8][4] = {};
        float mA = -1e30f, mB = -1e30f, lA = 0.f, lB = 0.f;
        int c_lo, c_hi;
        if (ph == 0) { c_lo = qt < 2 ? 2 - qt : 0; c_hi = 33 - qt; if (c_hi > 4) c_hi = 4; }
        else { c_lo = 0; c_hi = (ph == 1) ? 0 : 3; }
        int ntiles = (ph == 1) ? 4 : 8;
        int nt2max = ntiles >> 1;
        const float* Ksrc = (ph == 2) ? MEMV : K;
        const float* Vsrc = (ph == 2) ? MEMV : V;

        for (int c = c_lo; c <= c_hi; c++) {
            int key0 = (ph == 0) ? q0 - 128 + c * 64 : c * 64;
            bool needmask = (ph == 0) && (c != 2);
            __syncthreads();
#pragma unroll
            for (int rep = 0; rep < 8; rep++) {
                int idx = t + rep * 128;
                int row = idx >> 4, c4 = idx & 15;
                bool valid = (ph != 1) || (row < 32);
                size_t rowoff;
                if (ph == 2) rowoff = ((size_t)b * 256 + key0 + row) * 64;
                else if (ph == 1) rowoff = (hbase + (valid ? row * 64 : 0)) * 64;
                else rowoff = (hbase + key0 + row) * 64;
                float4 kv = valid ? *(const float4*)&Ksrc[rowoff + c4 * 4] : make_float4(0, 0, 0, 0);
                float4 vv = valid ? *(const float4*)&Vsrc[rowoff + c4 * 4] : make_float4(0, 0, 0, 0);
                uint32_t kh0 = CVT2(kv.x, kv.y), kh1 = CVT2(kv.z, kv.w);
                float2 kf0 = __bfloat1622float2(*(__nv_bfloat162*)&kh0);
                float2 kf1 = __bfloat1622float2(*(__nv_bfloat162*)&kh1);
                uint32_t kl0 = CVT2(kv.x - kf0.x, kv.y - kf0.y);
                uint32_t kl1 = CVT2(kv.z - kf1.x, kv.w - kf1.y);
                uint32_t vh0 = CVT2(vv.x, vv.y), vh1 = CVT2(vv.z, vv.w);
                float2 vf0 = __bfloat1622float2(*(__nv_bfloat162*)&vh0);
                float2 vf1 = __bfloat1622float2(*(__nv_bfloat162*)&vh1);
                uint32_t vl0 = CVT2(vv.x - vf0.x, vv.y - vf0.y);
                uint32_t vl1 = CVT2(vv.z - vf1.x, vv.w - vf1.y);
                int seg = c4 >> 1;
                uint32_t sw = row * 128 + ((seg ^ (row & 7)) << 4) + (c4 & 1) * 8;
                *(uint2*)(KH + sw) = make_uint2(kh0, kh1);
                *(uint2*)(KL + sw) = make_uint2(kl0, kl1);
                *(uint2*)(VH + sw) = make_uint2(vh0, vh1);
                *(uint2*)(VL + sw) = make_uint2(vl0, vl1);
            }
            __syncthreads();

            float sc[8][4] = {};
            for (int nt2 = 0; nt2 < nt2max; nt2++) {
                int krow = nt2 * 16 + (l & 7) + ((l >> 3) & 1) * 8;
#pragma unroll
                for (int ks = 0; ks < 4; ks++) {
                    int seg = ks * 2 + (l >> 4);
                    uint32_t off = krow * 128 + ((seg ^ (krow & 7)) << 4);
                    uint32_t bh[4], bl[4];
                    LDSM4(bh, sKH + off);
                    LDSM4(bl, sKL + off);
                    MMA_BF16(sc[2 * nt2], qh[ks], bh[0], bh[2]);
                    MMA_BF16(sc[2 * nt2], qh[ks], bl[0], bl[2]);
                    MMA_BF16(sc[2 * nt2], ql[ks], bh[0], bh[2]);
                    MMA_BF16(sc[2 * nt2 + 1], qh[ks], bh[1], bh[3]);
                    MMA_BF16(sc[2 * nt2 + 1], qh[ks], bl[1], bl[3]);
                    MMA_BF16(sc[2 * nt2 + 1], ql[ks], bh[1], bh[3]);
                }
            }

            for (int j = 0; j < ntiles; j++) {
                int gk = key0 + j * 8 + 2 * (l & 3);
                if (needmask) {
                    int dA0 = gqA - gk;     if (dA0 < 0) dA0 = -dA0;
                    int dA1 = gqA - gk - 1; if (dA1 < 0) dA1 = -dA1;
                    int dB0 = gqA + 8 - gk;     if (dB0 < 0) dB0 = -dB0;
                    int dB1 = gqA + 8 - gk - 1; if (dB1 < 0) dB1 = -dB1;
                    sc[j][0] = (dA0 <= WINR) ? sc[j][0] * ASCALE : -1e30f;
                    sc[j][1] = (dA1 <= WINR) ? sc[j][1] * ASCALE : -1e30f;
                    sc[j][2] = (dB0 <= WINR) ? sc[j][2] * ASCALE : -1e30f;
                    sc[j][3] = (dB1 <= WINR) ? sc[j][3] * ASCALE : -1e30f;
                } else if (ph == 1) {
                    bool ok = (j * 8 + 2 * (l & 3)) < 32;
                    sc[j][0] = ok ? sc[j][0] * ASCALE : -1e30f;
                    sc[j][1] = ok ? sc[j][1] * ASCALE : -1e30f;
                    sc[j][2] = ok ? sc[j][2] * ASCALE : -1e30f;
                    sc[j][3] = ok ? sc[j][3] * ASCALE : -1e30f;
                } else {
                    sc[j][0] *= ASCALE; sc[j][1] *= ASCALE;
                    sc[j][2] *= ASCALE; sc[j][3] *= ASCALE;
                }
            }

            float mxA = -1e30f, mxB = -1e30f;
            for (int j = 0; j < ntiles; j++) {
                mxA = fmaxf(mxA, fmaxf(sc[j][0], sc[j][1]));
                mxB = fmaxf(mxB, fmaxf(sc[j][2], sc[j][3]));
            }
            mxA = fmaxf(mxA, __shfl_xor_sync(0xffffffffu, mxA, 1));
            mxA = fmaxf(mxA, __shfl_xor_sync(0xffffffffu, mxA, 2));
            mxB = fmaxf(mxB, __shfl_xor_sync(0xffffffffu, mxB, 1));
            mxB = fmaxf(mxB, __shfl_xor_sync(0xffffffffu, mxB, 2));
            float nmA = fmaxf(mA, mxA), nmB = fmaxf(mB, mxB);
            float fA = __expf(mA - nmA), fB = __expf(mB - nmB);
            mA = nmA; mB = nmB;
            float sA = 0.f, sB = 0.f;
            for (int j = 0; j < ntiles; j++) {
                sc[j][0] = __expf(sc[j][0] - nmA);
                sc[j][1] = __expf(sc[j][1] - nmA);
                sc[j][2] = __expf(sc[j][2] - nmB);
                sc[j][3] = __expf(sc[j][3] - nmB);
                sA += sc[j][0] + sc[j][1];
                sB += sc[j][2] + sc[j][3];
            }
            sA += __shfl_xor_sync(0xffffffffu, sA, 1);
            sA += __shfl_xor_sync(0xffffffffu, sA, 2);
            sB += __shfl_xor_sync(0xffffffffu, sB, 1);
            sB += __shfl_xor_sync(0xffffffffu, sB, 2);
            lA = lA * fA + sA;
            lB = lB * fB + sB;
#pragma unroll
            for (int j = 0; j < 8; j++) {
                acc[j][0] *= fA; acc[j][1] *= fA;
                acc[j][2] *= fB; acc[j][3] *= fB;
            }

            for (int kt = 0; kt < nt2max; kt++) {
                uint32_t ah[4], al_[4];
                ah[0] = CVT2(sc[2 * kt][0], sc[2 * kt][1]);
                ah[1] = CVT2(sc[2 * kt][2], sc[2 * kt][3]);
                ah[2] = CVT2(sc[2 * kt + 1][0], sc[2 * kt + 1][1]);
                ah[3] = CVT2(sc[2 * kt + 1][2], sc[2 * kt + 1][3]);
                {
                    float2 r0 = __bfloat1622float2(*(__nv_bfloat162*)&ah[0]);
                    float2 r1 = __bfloat1622float2(*(__nv_bfloat162*)&ah[1]);
                    float2 r2 = __bfloat1622float2(*(__nv_bfloat162*)&ah[2]);
                    float2 r3 = __bfloat1622float2(*(__nv_bfloat162*)&ah[3]);
                    al_[0] = CVT2(sc[2 * kt][0] - r0.x, sc[2 * kt][1] - r0.y);
                    al_[1] = CVT2(sc[2 * kt][2] - r1.x, sc[2 * kt][3] - r1.y);
                    al_[2] = CVT2(sc[2 * kt + 1][0] - r2.x, sc[2 * kt + 1][1] - r2.y);
                    al_[3] = CVT2(sc[2 * kt + 1][2] - r3.x, sc[2 * kt + 1][3] - r3.y);
                }
                int vrow = kt * 16 + (l & 7) + ((l >> 3) & 1) * 8;
#pragma unroll
                for (int jn2 = 0; jn2 < 4; jn2++) {
                    int seg = jn2 * 2 + (l >> 4);
                    uint32_t off = vrow * 128 + ((seg ^ (vrow & 7)) << 4);
                    uint32_t bh[4], bl[4];
                    LDSM4T(bh, sVH + off);
                    LDSM4T(bl, sVL + off);
                    MMA_BF16(acc[2 * jn2], ah, bh[0], bh[1]);
                    MMA_BF16(acc[2 * jn2], ah, bl[0], bl[1]);
                    MMA_BF16(acc[2 * jn2], al_, bh[0], bh[1]);
                    MMA_BF16(acc[2 * jn2 + 1], ah, bh[2], bh[3]);
                    MMA_BF16(acc[2 * jn2 + 1], ah, bl[2], bl[3]);
                    MMA_BF16(acc[2 * jn2 + 1], al_, bh[2], bh[3]);
                }
            }
        }

        float invA = 1.f / lA, invB = 1.f / lB;
#pragma unroll
        for (int j = 0; j < 8; j++) {
            int hd = j * 8 + 2 * (l & 3);
            size_t offA = (hbase + gqA) * 64 + hd;
            size_t offB = offA + 8 * 64;
            float2 oA = make_float2(acc[j][0] * invA, acc[j][1] * invA);
            float2 oB = make_float2(acc[j][2] * invB, acc[j][3] * invB);
            if (ph > 0) {
                float2 pA = *(float2*)&O[offA]; oA.x += pA.x; oA.y += pA.y;
                float2 pB = *(float2*)&O[offB]; oB.x += pB.x; oB.y += pB.y;
            }
            *(float2*)&O[offA] = oA;
            *(float2*)&O[offB] = oB;
        }
    }
}

// ---------------------------------------------------------------------------
// convert out_W and the 3 V weight matrices -> bf16 hi/lo.
// blocks 0..1023 -> W (1024x1024), 1024..1215 -> V (3x1024x64).
// ---------------------------------------------------------------------------
__global__ __launch_bounds__(256) void k_cvt_w(const float* __restrict__ W,
                                               P3 Vs,
                                               __nv_bfloat16* __restrict__ Wh,
                                               __nv_bfloat16* __restrict__ Wl,
                                               __nv_bfloat16* __restrict__ Vh,
                                               __nv_bfloat16* __restrict__ Vl) {
    int bid = blockIdx.x;
    int t = threadIdx.x;
    float4 v;
    __nv_bfloat16 *Hd, *Ld;
    size_t dst;
    if (bid < 1024) {
        int idx = bid * 256 + t;
        v = *(const float4*)&W[(size_t)idx * 4];
        dst = (size_t)idx * 4;
        Hd = Wh; Ld = Wl;
    } else {
        int idx = (bid - 1024) * 256 + t;     // over 3*16384 float4
        int p = idx >> 14, rem = idx & 16383;
        v = *(const float4*)&sel(Vs, p)[(size_t)rem * 4];
        dst = ((size_t)p << 16) + (size_t)rem * 4;
        Hd = Vh; Ld = Vl;
    }
    __nv_bfloat162 h0 = __floats2bfloat162_rn(v.x, v.y);
    __nv_bfloat162 h1 = __floats2bfloat162_rn(v.z, v.w);
    __nv_bfloat162 l0 = __floats2bfloat162_rn(v.x - __bfloat162float(h0.x),
                                              v.y - __bfloat162float(h0.y));
    __nv_bfloat162 l1 = __floats2bfloat162_rn(v.z - __bfloat162float(h1.x),
                                              v.w - __bfloat162float(h1.y));
    *(uint32_t*)&Hd[dst]     = *(uint32_t*)&h0;
    *(uint32_t*)&Hd[dst + 2] = *(uint32_t*)&h1;
    *(uint32_t*)&Ld[dst]     = *(uint32_t*)&l0;
    *(uint32_t*)&Ld[dst + 2] = *(uint32_t*)&l1;
}

// ---------------------------------------------------------------------------
// out = fused(C) @ W^T + b via mma.sync bf16x3 (R14 version, fused A split).
// ---------------------------------------------------------------------------
#define OP_LDG_A(kc)                                                           \
    do {                                                                       \
        int _hh = (kc) >> 1;                                                   \
        int _hdb = ((kc) & 1) * 32;                                            \
        _Pragma("unroll")                                                      \
        for (int rep = 0; rep < 2; rep++) {                                    \
            int idx = t + rep * 256;                                           \
            int row = idx >> 2, seg = idx & 3;                                 \
            int m = m0 + row;                                                  \
            int bi = m >> 11, ni = m & 2047;                                   \
            const float* s = &C[((size_t)(bi * 16 + _hh) * 2048 + ni) * 64     \
                                + _hdb + seg * 8];                             \
            av[rep][0] = *(const float4*)s;                                    \
            av[rep][1] = *(const float4*)(s + 4);                              \
        }                                                                      \
    } while (0)

#define OP_STS_A(s)                                                            \
    do {                                                                       \
        _Pragma("unroll")                                                      \
        for (int rep = 0; rep < 2; rep++) {                                    \
            int idx = t + rep * 256;                                           \
            int row = idx >> 2, seg = idx & 3;                                 \
            uint32_t h0 = CVT2(av[rep][0].x, av[rep][0].y);                    \
            uint32_t h1 = CVT2(av[rep][0].z, av[rep][0].w);                    \
            uint32_t h2 = CVT2(av[rep][1].x, av[rep][1].y);                    \
            uint32_t h3 = CVT2(av[rep][1].z, av[rep][1].w);                    \
            float2 f0 = __bfloat1622float2(*(__nv_bfloat162*)&h0);             \
            float2 f1 = __bfloat1622float2(*(__nv_bfloat162*)&h1);             \
            float2 f2 = __bfloat1622float2(*(__nv_bfloat162*)&h2);             \
            float2 f3 = __bfloat1622float2(*(__nv_bfloat162*)&h3);             \
            uint32_t l0 = CVT2(av[rep][0].x - f0.x, av[rep][0].y - f0.y);      \
            uint32_t l1 = CVT2(av[rep][0].z - f1.x, av[rep][0].w - f1.y);      \
            uint32_t l2 = CVT2(av[rep][1].x - f2.x, av[rep][1].y - f2.y);      \
            uint32_t l3 = CVT2(av[rep][1].z - f3.x, av[rep][1].w - f3.y);      \
            uint32_t off = (s) * 40960 + row * 80 + seg * 16;                  \
            *(uint4*)(smc + off)         = make_uint4(h0, h1, h2, h3);         \
            *(uint4*)(smc + 10240 + off) = make_uint4(l0, l1, l2, l3);         \
        }                                                                      \
    } while (0)

#define OP_LOAD_W(kc, s)                                                       \
    do {                                                                       \
        uint32_t _base = sb + (s) * 40960 + 20480;                             \
        _Pragma("unroll")                                                      \
        for (int rep = 0; rep < 4; rep++) {                                    \
            int idx = t + rep * 256;                                           \
            int plane = idx >> 9;                                              \
            int rem = idx & 511;                                               \
            int row = rem >> 2, seg = rem & 3;                                 \
            uint32_t dst = _base + plane * 10240 + row * 80 + seg * 16;        \
            const __nv_bfloat16* src = plane ? Wlg : Whg;                      \
            CP_ASYNC16(dst, &src[(size_t)(n0 + row) * 1024 + (kc) * 32 + seg * 8]); \
        }                                                                      \
    } while (0)

__global__ __launch_bounds__(256, 2) void k_outproj_mma(const float* __restrict__ C,
                                                        const __nv_bfloat16* __restrict__ Whg,
                                                        const __nv_bfloat16* __restrict__ Wlg,
                                                        const float* __restrict__ bias,
                                                        float* __restrict__ out) {
    extern __shared__ char smc[];
    uint32_t sb = smem_u32(smc);
    int t = threadIdx.x;
    int wid = t >> 5, l = t & 31;
    int wm = wid & 3, wn = wid >> 2;
    int m0 = blockIdx.x * 128, n0 = blockIdx.y * 128;

    float acc[2][8][4] = {};
    float4 av[2][2];

    int row_a = wm * 32 + (l & 15);
    int sega  = (l >> 4);
    int row_b = wn * 64 + ((l >> 4) & 1) * 8 + (l & 7);
    int segb  = ((l >> 3) & 1);

    OP_LDG_A(0);
    OP_LOAD_W(0, 0);
    CP_COMMIT();

    for (int kc = 0; kc < 32; kc++) {
        OP_STS_A(kc & 1);
        if (kc + 1 < 32) {
            OP_LOAD_W(kc + 1, (kc + 1) & 1);
            CP_COMMIT();
            OP_LDG_A(kc + 1);
            CP_WAIT(1);
        } else {
            CP_WAIT(0);
        }
        __syncthreads();
        uint32_t base = sb + (kc & 1) * 40960;

#pragma unroll
        for (int ks = 0; ks < 2; ks++) {
            uint32_t ah[2][4], al_[2][4];
#pragma unroll
            for (int mt = 0; mt < 2; mt++) {
                int ra = row_a + mt * 16;
                uint32_t off = ra * 80 + (ks * 2 + sega) * 16;
                LDSM4(ah[mt], base + off);
                LDSM4(al_[mt], base + 10240 + off);
            }
#pragma unroll
            for (int ntp = 0; ntp < 4; ntp++) {
                int rb = row_b + ntp * 16;
                uint32_t off = rb * 80 + (ks * 2 + segb) * 16;
                uint32_t bh[4], bl[4];
                LDSM4(bh, base + 20480 + off);
                LDSM4(bl, base + 30720 + off);
#pragma unroll
                for (int mt = 0; mt < 2; mt++) {
#pragma unroll
                    for (int half = 0; half < 2; half++) {
                        float* d = acc[mt][ntp * 2 + half];
                        MMA_BF16(d, ah[mt], bh[half * 2], bh[half * 2 + 1]);
                        MMA_BF16(d, ah[mt], bl[half * 2], bl[half * 2 + 1]);
                        MMA_BF16(d, al_[mt], bh[half * 2], bh[half * 2 + 1]);
                    }
                }
            }
        }
        __syncthreads();
    }

#pragma unroll
    for (int mt = 0; mt < 2; mt++) {
        int r0 = m0 + wm * 32 + mt * 16 + (l >> 2);
#pragma unroll
        for (int nt = 0; nt < 8; nt++) {
            int c = n0 + wn * 64 + nt * 8 + 2 * (l & 3);
            float b0 = bias[c], b1 = bias[c + 1];
            float* d = acc[mt][nt];
            *(float2*)&out[(size_t)r0 * 1024 + c] = make_float2(d[0] + b0, d[1] + b1);
            *(float2*)&out[(size_t)(r0 + 8) * 1024 + c] = make_float2(d[2] + b0, d[3] + b1);
        }
    }
}

// ---------------------------------------------------------------------------
__global__ __launch_bounds__(128) void k_heads(const float* __restrict__ C,
                                               const float* __restrict__ tW, const float* __restrict__ tb,
                                               const float* __restrict__ iW, const float* __restrict__ ib,
                                               const float* __restrict__ cW, const float* __restrict__ cb,
                                               float* __restrict__ out) {
    int r = blockIdx.x;
    int b = r >> 11, n = r & 2047;
    __shared__ float last[64];
    int t = threadIdx.x;
    if (t < 64) last[t] = C[((size_t)(b * 16) * 2048 + n) * 64 + t];
    __syncthreads();
    if (t < 2) {
        float s = tb[t];
        for (int k = 0; k < 64; k++) s += last[k] * tW[t * 64 + k];
        out[4194304 + (size_t)r * 2 + t] = s;
    } else if (t < 66) {
        int j = t - 2;
        float s = ib[j];
        for (int k = 0; k < 64; k++) s += last[k] * iW[j * 64 + k];
        out[4202496 + (size_t)r * 64 + j] = s;
    } else if (t < 98) {
        int j = t - 66;
        float s = cb[j];
        for (int k = 0; k < 64; k++) s += last[k] * cW[j * 64 + k];
        out[4464640 + (size_t)r * 32 + j] = s;
    }
}

// ---------------------------------------------------------------------------
extern "C" void kernel_launch(void* const* d_in, const int* in_sizes, int n_in,
                              void* d_out, int out_size) {
    const float* x   = (const float*)d_in[0];
    const float* mem = (const float*)d_in[1];
    P3 Us  = { (const float*)d_in[2],  (const float*)d_in[8],  (const float*)d_in[14] };
    P3 Vs  = { (const float*)d_in[3],  (const float*)d_in[9],  (const float*)d_in[15] };
    P3 als = { (const float*)d_in[4],  (const float*)d_in[10], (const float*)d_in[16] };
    P3 As  = { (const float*)d_in[5],  (const float*)d_in[11], (const float*)d_in[17] };
    P3 Bls = { (const float*)d_in[6],  (const float*)d_in[12], (const float*)d_in[18] };
    P3 bis = { (const float*)d_in[7],  (const float*)d_in[13], (const float*)d_in[19] };
    const float* outW = (const float*)d_in[20];
    const float* outb = (const float*)d_in[21];
    const float* tW = (const float*)d_in[22];
    const float* tb = (const float*)d_in[23];
    const float* iW = (const float*)d_in[24];
    const float* ib = (const float*)d_in[25];
    const float* cW = (const float*)d_in[26];
    const float* cb = (const float*)d_in[27];
    float* out = (float*)d_out;

    void *pL, *pQKV, *pC, *pTh, *pTl, *pVh, *pVl, *pWh, *pWl;
    cudaGetSymbolAddress(&pL, g_l);
    cudaGetSymbolAddress(&pQKV, g_qkv);
    cudaGetSymbolAddress(&pC, g_comb);
    cudaGetSymbolAddress(&pTh, g_th);
    cudaGetSymbolAddress(&pTl, g_tl);
    cudaGetSymbolAddress(&pVh, g_vh);
    cudaGetSymbolAddress(&pVl, g_vl);
    cudaGetSymbolAddress(&pWh, g_wh);
    cudaGetSymbolAddress(&pWl, g_wl);
    float* Lb = (float*)pL;
    float* QKV = (float*)pQKV;
    float* Cb = (float*)pC;
    const size_t QSZ = (size_t)BATCH * NHEAD * NSEQ * 64;

    k_xu<<<dim3(64, 3), 128>>>(x, Us, als, (__nv_bfloat16*)pTh, (__nv_bfloat16*)pTl);
    k_lora<<<4096, 128>>>(x, As, Lb);
    k_cvt_w<<<1216, 256>>>(outW, Vs,
                           (__nv_bfloat16*)pWh, (__nv_bfloat16*)pWl,
                           (__nv_bfloat16*)pVh, (__nv_bfloat16*)pVl);

    const int SMEM_PJ = 75776;
    cudaFuncSetAttribute(k_proj_mma, cudaFuncAttributeMaxDynamicSharedMemorySize, SMEM_PJ);
    k_proj_mma<<<dim3(32, 8, 3), 256, SMEM_PJ>>>((const __nv_bfloat16*)pTh,
                                                 (const __nv_bfloat16*)pTl,
                                                 (const __nv_bfloat16*)pVh,
                                                 (const __nv_bfloat16*)pVl,
                                                 Lb, Bls, bis, QKV);

    const int SMEM_ATTN = 32768;
    cudaFuncSetAttribute(k_attn_mma, cudaFuncAttributeMaxDynamicSharedMemorySize, SMEM_ATTN);
    k_attn_mma<<<dim3(32, 16, 2), 128, SMEM_ATTN>>>(QKV, QKV + QSZ, QKV + 2 * QSZ, mem, Cb);

    const int SMEM_OP = 81920;
    cudaFuncSetAttribute(k_outproj_mma, cudaFuncAttributeMaxDynamicSharedMemorySize, SMEM_OP);
    k_outproj_mma<<<dim3(32, 8), 256, SMEM_OP>>>(Cb,
                                                 (const __nv_bfloat16*)pWh,
                                                 (const __nv_bfloat16*)pWl,
                                                 outb, out);

    k_heads<<<4096, 128>>>(Cb, tW, tb, iW, ib, cW, cb, out);
}

// round 16
// speedup vs baseline: 1.0917x; 1.0317x over previous
#include <cuda_runtime.h>
#include <cuda_bf16.h>
#include <math.h>
#include <stdint.h>

#define NSEQ 2048
#define BATCH 2
#define NHEAD 16
#define MROWS 4096
#define WINR 128
#define ASCALE 0.125f

typedef unsigned long long u64;
struct P3 { const float* a; const float* b; const float* c; };
__device__ __forceinline__ const float* sel(P3 p, int i) {
    return i == 0 ? p.a : (i == 1 ? p.b : p.c);
}

__device__ __forceinline__ u64 PK2(float lo, float hi) {
    u64 r; asm("mov.b64 %0,{%1,%2};" : "=l"(r) : "f"(lo), "f"(hi)); return r;
}
__device__ __forceinline__ u64 DUP(float v) { return PK2(v, v); }
__device__ __forceinline__ void FMA2(u64& d, u64 a, u64 b) {
    asm("fma.rn.f32x2 %0,%1,%2,%0;" : "+l"(d) : "l"(a), "l"(b));
}
__device__ __forceinline__ float2 UPK(u64 v) {
    float2 f; asm("mov.b64 {%0,%1},%2;" : "=f"(f.x), "=f"(f.y) : "l"(v)); return f;
}

__device__ __forceinline__ uint32_t smem_u32(const void* p) {
    uint32_t a;
    asm("{ .reg .u64 t; cvta.to.shared.u64 t, %1; cvt.u32.u64 %0, t; }" : "=r"(a) : "l"(p));
    return a;
}

// ---- portable tensor-core + async-copy ops (sm_80+ baseline PTX) ----
__device__ __forceinline__ void MMA_BF16(float* d, const uint32_t* a, uint32_t b0, uint32_t b1) {
    asm volatile(
        "mma.sync.aligned.m16n8k16.row.col.f32.bf16.bf16.f32 "
        "{%0,%1,%2,%3}, {%4,%5,%6,%7}, {%8,%9}, {%0,%1,%2,%3};"
        : "+f"(d[0]), "+f"(d[1]), "+f"(d[2]), "+f"(d[3])
        : "r"(a[0]), "r"(a[1]), "r"(a[2]), "r"(a[3]), "r"(b0), "r"(b1));
}
__device__ __forceinline__ void LDSM4(uint32_t* r, uint32_t addr) {
    asm volatile("ldmatrix.sync.aligned.m8n8.x4.shared.b16 {%0,%1,%2,%3}, [%4];"
                 : "=r"(r[0]), "=r"(r[1]), "=r"(r[2]), "=r"(r[3]) : "r"(addr));
}
__device__ __forceinline__ void LDSM4T(uint32_t* r, uint32_t addr) {
    asm volatile("ldmatrix.sync.aligned.m8n8.x4.trans.shared.b16 {%0,%1,%2,%3}, [%4];"
                 : "=r"(r[0]), "=r"(r[1]), "=r"(r[2]), "=r"(r[3]) : "r"(addr));
}
__device__ __forceinline__ uint32_t CVT2(float lo, float hi) {
    uint32_t r; asm("cvt.rn.bf16x2.f32 %0, %1, %2;" : "=r"(r) : "f"(hi), "f"(lo)); return r;
}
#define CP_ASYNC16(dst, src) \
    asm volatile("cp.async.ca.shared.global [%0], [%1], 16;" :: "r"(dst), "l"(src) : "memory")
#define CP_COMMIT() asm volatile("cp.async.commit_group;" ::: "memory")
#define CP_WAIT(n)  asm volatile("cp.async.wait_group %0;" :: "n"(n) : "memory")

// ---------------- scratch ----------------
__device__ float g_l[3 * MROWS * 4];
__device__ float g_qkv[3 * BATCH * NHEAD * NSEQ * 64];
__device__ float g_comb[BATCH * NHEAD * NSEQ * 64];
__device__ __nv_bfloat16 g_th[3 * MROWS * 64];
__device__ __nv_bfloat16 g_tl[3 * MROWS * 64];
__device__ __nv_bfloat16 g_vh[3 * 1024 * 64];
__device__ __nv_bfloat16 g_vl[3 * 1024 * 64];
__device__ __nv_bfloat16 g_wh[1024 * 1024];
__device__ __nv_bfloat16 g_wl[1024 * 1024];

// ---------------------------------------------------------------------------
// t = x @ U * alpha -> bf16 hi/lo planes, AND l = x @ A (rank-4, fp32) fused.
// 64x64 tile, 128 thr, 8x4 micro.  grid (64, 3).
// ---------------------------------------------------------------------------
__global__ __launch_bounds__(128) void k_xu(const float* __restrict__ X,
                                            P3 Us, P3 als, P3 As,
                                            __nv_bfloat16* __restrict__ TH,
                                            __nv_bfloat16* __restrict__ TL,
                                            float* __restrict__ Lb) {
    __shared__ float a_s[64][68];
    __shared__ float b_s[64][68];
    __shared__ float A_s[64][4];
    int p = blockIdx.y;
    const float* U = sel(Us, p);
    const float* alpha = sel(als, p);
    const float* Ap = sel(As, p);
    __nv_bfloat16* Th = TH + (size_t)p * MROWS * 64;
    __nv_bfloat16* Tl = TL + (size_t)p * MROWS * 64;
    int t = threadIdx.x;
    int m0 = blockIdx.x * 64;
    int tm = t >> 4, tn4 = t & 15;
    int lm = t >> 1, lj2 = (t & 1) * 2;         // lora: row, col-pair
    u64 acc2[8][2] = {};
    float lacc0 = 0.f, lacc1 = 0.f;
    for (int k0 = 0; k0 < 1024; k0 += 64) {
#pragma unroll
        for (int rep = 0; rep < 8; rep++) {
            int fidx = t + rep * 128;
            int m = fidx >> 4, kq = fidx & 15;
            float4 v = *(const float4*)&X[(size_t)(m0 + m) * 1024 + k0 + kq * 4];
            a_s[kq * 4 + 0][m] = v.x; a_s[kq * 4 + 1][m] = v.y;
            a_s[kq * 4 + 2][m] = v.z; a_s[kq * 4 + 3][m] = v.w;
        }
#pragma unroll
        for (int rep = 0; rep < 8; rep++) {
            int fidx = t + rep * 128;
            int kk = fidx >> 4, nq = fidx & 15;
            *(float4*)&b_s[kk][nq * 4] = *(const float4*)&U[(size_t)(k0 + kk) * 64 + nq * 4];
        }
#pragma unroll
        for (int rep = 0; rep < 2; rep++) {       // A chunk: 64x4
            int e = t + rep * 128;
            int kk = e >> 2, j = e & 3;
            A_s[kk][j] = Ap[(size_t)(k0 + kk) * 4 + j];
        }
        __syncthreads();
#pragma unroll 8
        for (int kk = 0; kk < 64; kk++) {
            float4 a0 = *(const float4*)&a_s[kk][tm * 8];
            float4 a1 = *(const float4*)&a_s[kk][tm * 8 + 4];
            ulonglong2 bp = *(const ulonglong2*)&b_s[kk][tn4 * 4];
            float aa[8] = {a0.x, a0.y, a0.z, a0.w, a1.x, a1.y, a1.z, a1.w};
#pragma unroll
            for (int i = 0; i < 8; i++) {
                u64 d = DUP(aa[i]);
                FMA2(acc2[i][0], d, bp.x);
                FMA2(acc2[i][1], d, bp.y);
            }
        }
        // lora accumulation: thread t owns row lm, cols lj2, lj2+1
#pragma unroll 8
        for (int kk = 0; kk < 64; kk++) {
            float xv = a_s[kk][lm];
            lacc0 += xv * A_s[kk][lj2];
            lacc1 += xv * A_s[kk][lj2 + 1];
        }
        __syncthreads();
    }
    float al0 = alpha[tn4 * 4 + 0], al1 = alpha[tn4 * 4 + 1];
    float al2 = alpha[tn4 * 4 + 2], al3 = alpha[tn4 * 4 + 3];
#pragma unroll
    for (int i = 0; i < 8; i++) {
        float2 c0 = UPK(acc2[i][0]), c1 = UPK(acc2[i][1]);
        float v0 = c0.x * al0, v1 = c0.y * al1, v2 = c1.x * al2, v3 = c1.y * al3;
        uint32_t h0 = CVT2(v0, v1), h1 = CVT2(v2, v3);
        float2 f0 = __bfloat1622float2(*(__nv_bfloat162*)&h0);
        float2 f1 = __bfloat1622float2(*(__nv_bfloat162*)&h1);
        uint32_t l0 = CVT2(v0 - f0.x, v1 - f0.y);
        uint32_t l1 = CVT2(v2 - f1.x, v3 - f1.y);
        size_t off = (size_t)(m0 + tm * 8 + i) * 64 + tn4 * 4;
        *(uint2*)&Th[off] = make_uint2(h0, h1);
        *(uint2*)&Tl[off] = make_uint2(l0, l1);
    }
    *(float2*)&Lb[(size_t)p * MROWS * 4 + (size_t)(m0 + lm) * 4 + lj2] =
        make_float2(lacc0, lacc1);
}

// ---------------------------------------------------------------------------
// proj via mma.sync bf16x3: out = T @ V^T (K=64) + l@B (fp32 epi) + bias.
// ---------------------------------------------------------------------------
__global__ __launch_bounds__(256, 2) void k_proj_mma(const __nv_bfloat16* __restrict__ THg,
                                                     const __nv_bfloat16* __restrict__ TLg,
                                                     const __nv_bfloat16* __restrict__ VHg,
                                                     const __nv_bfloat16* __restrict__ VLg,
                                                     const float* __restrict__ Lb,
                                                     P3 Bls, P3 bis,
                                                     float* __restrict__ QKV) {
    extern __shared__ char smp[];
    uint32_t sb = smem_u32(smp);
    const int TH = 0, TL = 18432, VH = 36864, VL = 55296, BLS = 73728;
    float* blS = (float*)(smp + BLS);
    int p = blockIdx.z;
    const __nv_bfloat16* Tph = THg + (size_t)p * MROWS * 64;
    const __nv_bfloat16* Tpl = TLg + (size_t)p * MROWS * 64;
    const __nv_bfloat16* Vph = VHg + (size_t)p * 1024 * 64;
    const __nv_bfloat16* Vpl = VLg + (size_t)p * 1024 * 64;
    const float* L = Lb + (size_t)p * MROWS * 4;
    const float* Blora = sel(Bls, p);
    const float* bias = sel(bis, p);
    float* O = QKV + (size_t)p * BATCH * NHEAD * NSEQ * 64;

    int t = threadIdx.x;
    int wid = t >> 5, l = t & 31;
    int wm = wid & 3, wn = wid >> 2;
    int m0 = blockIdx.x * 128, n0 = blockIdx.y * 128;

#pragma unroll
    for (int rep = 0; rep < 16; rep++) {
        int idx = t + rep * 256;
        int plane = idx >> 10;
        int rem = idx & 1023;
        int row = rem >> 3, seg = rem & 7;
        uint32_t dst = sb + plane * 18432 + row * 144 + seg * 16;
        const __nv_bfloat16* src;
        size_t g;
        if (plane == 0)      { src = Tph; g = (size_t)(m0 + row) * 64; }
        else if (plane == 1) { src = Tpl; g = (size_t)(m0 + row) * 64; }
        else if (plane == 2) { src = Vph; g = (size_t)(n0 + row) * 64; }
        else                 { src = Vpl; g = (size_t)(n0 + row) * 64; }
        CP_ASYNC16(dst, &src[g + seg * 8]);
    }
    if (t < 128) {
#pragma unroll
        for (int j = 0; j < 4; j++)
            blS[j * 128 + t] = Blora[(size_t)j * 1024 + n0 + t];
    }
    CP_COMMIT();
    CP_WAIT(0);
    __syncthreads();

    float acc[2][8][4] = {};
    int row_a = wm * 32 + (l & 15);
    int sega  = (l >> 4);
    int row_b = wn * 64 + ((l >> 4) & 1) * 8 + (l & 7);
    int segb  = ((l >> 3) & 1);

#pragma unroll
    for (int ks = 0; ks < 4; ks++) {
        uint32_t ah[2][4], al_[2][4];
#pragma unroll
        for (int mt = 0; mt < 2; mt++) {
            int ra = row_a + mt * 16;
            uint32_t off = ra * 144 + (ks * 2 + sega) * 16;
            LDSM4(ah[mt], sb + TH + off);
            LDSM4(al_[mt], sb + TL + off);
        }
#pragma unroll
        for (int ntp = 0; ntp < 4; ntp++) {
            int rb = row_b + ntp * 16;
            uint32_t off = rb * 144 + (ks * 2 + segb) * 16;
            uint32_t bh[4], bl[4];
            LDSM4(bh, sb + VH + off);
            LDSM4(bl, sb + VL + off);
#pragma unroll
            for (int mt = 0; mt < 2; mt++) {
#pragma unroll
                for (int half = 0; half < 2; half++) {
                    float* d = acc[mt][ntp * 2 + half];
                    MMA_BF16(d, ah[mt], bh[half * 2], bh[half * 2 + 1]);
                    MMA_BF16(d, ah[mt], bl[half * 2], bl[half * 2 + 1]);
                    MMA_BF16(d, al_[mt], bh[half * 2], bh[half * 2 + 1]);
                }
            }
        }
    }

#pragma unroll
    for (int mt = 0; mt < 2; mt++) {
        int r0 = m0 + wm * 32 + mt * 16 + (l >> 2);
        int r1 = r0 + 8;
        float lv0[4], lv1[4];
#pragma unroll
        for (int j = 0; j < 4; j++) {
            lv0[j] = L[(size_t)r0 * 4 + j];
            lv1[j] = L[(size_t)r1 * 4 + j];
        }
#pragma unroll
        for (int nt = 0; nt < 8; nt++) {
            int c = n0 + wn * 64 + nt * 8 + 2 * (l & 3);
            int cl = c - n0;
            float b0 = bias[c], b1 = bias[c + 1];
            float l00 = 0.f, l01 = 0.f, l10 = 0.f, l11 = 0.f;
#pragma unroll
            for (int j = 0; j < 4; j++) {
                float B0 = blS[j * 128 + cl], B1 = blS[j * 128 + cl + 1];
                l00 += lv0[j] * B0; l01 += lv0[j] * B1;
                l10 += lv1[j] * B0; l11 += lv1[j] * B1;
            }
            float* d = acc[mt][nt];
            int h = c >> 6, hd = c & 63;
            size_t o0 = ((size_t)((r0 >> 11) * 16 + h) * 2048 + (r0 & 2047)) * 64 + hd;
            size_t o1 = ((size_t)((r1 >> 11) * 16 + h) * 2048 + (r1 & 2047)) * 64 + hd;
            *(float2*)&O[o0] = make_float2(d[0] + l00 + b0, d[1] + l01 + b1);
            *(float2*)&O[o1] = make_float2(d[2] + l10 + b0, d[3] + l11 + b1);
        }
    }
}

// ---------------------------------------------------------------------------
// fused 3-branch flash attention via mma.sync bf16x3 (R7/R10 verbatim).
// ---------------------------------------------------------------------------
__global__ __launch_bounds__(128) void k_attn_mma(const float* __restrict__ Q,
                                                  const float* __restrict__ K,
                                                  const float* __restrict__ V,
                                                  const float* __restrict__ MEMV,
                                                  float* __restrict__ O) {
    extern __shared__ char sma[];
    char* KH = sma;
    char* KL = sma + 8192;
    char* VH = sma + 16384;
    char* VL = sma + 24576;
    uint32_t sKH = smem_u32(KH), sKL = smem_u32(KL);
    uint32_t sVH = smem_u32(VH), sVL = smem_u32(VL);

    int t = threadIdx.x;
    int w = t >> 5, l = t & 31;
    int qt = blockIdx.x, h = blockIdx.y, b = blockIdx.z;
    int q0 = qt * 64;
    size_t hbase = (size_t)(b * 16 + h) * 2048;

#pragma unroll
    for (int rep = 0; rep < 8; rep++) {
        int idx = t + rep * 128;
        int row = idx >> 4, c4 = idx & 15;
        float4 v = *(const float4*)&Q[(hbase + q0 + row) * 64 + c4 * 4];
        uint32_t h0 = CVT2(v.x, v.y), h1 = CVT2(v.z, v.w);
        float2 f0 = __bfloat1622float2(*(__nv_bfloat162*)&h0);
        float2 f1 = __bfloat1622float2(*(__nv_bfloat162*)&h1);
        uint32_t l0 = CVT2(v.x - f0.x, v.y - f0.y);
        uint32_t l1 = CVT2(v.z - f1.x, v.w - f1.y);
        int seg = c4 >> 1;
        uint32_t sw = row * 128 + ((seg ^ (row & 7)) << 4) + (c4 & 1) * 8;
        *(uint2*)(KH + sw) = make_uint2(h0, h1);
        *(uint2*)(KL + sw) = make_uint2(l0, l1);
    }
    __syncthreads();

    uint32_t qh[4][4], ql[4][4];
    {
        int qrow = w * 16 + (l & 7) + ((l >> 3) & 1) * 8;
#pragma unroll
        for (int ks = 0; ks < 4; ks++) {
            int seg = ks * 2 + (l >> 4);
            uint32_t off = qrow * 128 + ((seg ^ (qrow & 7)) << 4);
            LDSM4(qh[ks], sKH + off);
            LDSM4(ql[ks], sKL + off);
        }
    }

    int gqA = q0 + w * 16 + (l >> 2);

    for (int ph = 0; ph < 3; ph++) {
        float acc[8][4] = {};
        float mA = -1e30f, mB = -1e30f, lA = 0.f, lB = 0.f;
        int c_lo, c_hi;
        if (ph == 0) { c_lo = qt < 2 ? 2 - qt : 0; c_hi = 33 - qt; if (c_hi > 4) c_hi = 4; }
        else { c_lo = 0; c_hi = (ph == 1) ? 0 : 3; }
        int ntiles = (ph == 1) ? 4 : 8;
        int nt2max = ntiles >> 1;
        const float* Ksrc = (ph == 2) ? MEMV : K;
        const float* Vsrc = (ph == 2) ? MEMV : V;

        for (int c = c_lo; c <= c_hi; c++) {
            int key0 = (ph == 0) ? q0 - 128 + c * 64 : c * 64;
            bool needmask = (ph == 0) && (c != 2);
            __syncthreads();
#pragma unroll
            for (int rep = 0; rep < 8; rep++) {
                int idx = t + rep * 128;
                int row = idx >> 4, c4 = idx & 15;
                bool valid = (ph != 1) || (row < 32);
                size_t rowoff;
                if (ph == 2) rowoff = ((size_t)b * 256 + key0 + row) * 64;
                else if (ph == 1) rowoff = (hbase + (valid ? row * 64 : 0)) * 64;
                else rowoff = (hbase + key0 + row) * 64;
                float4 kv = valid ? *(const float4*)&Ksrc[rowoff + c4 * 4] : make_float4(0, 0, 0, 0);
                float4 vv = valid ? *(const float4*)&Vsrc[rowoff + c4 * 4] : make_float4(0, 0, 0, 0);
                uint32_t kh0 = CVT2(kv.x, kv.y), kh1 = CVT2(kv.z, kv.w);
                float2 kf0 = __bfloat1622float2(*(__nv_bfloat162*)&kh0);
                float2 kf1 = __bfloat1622float2(*(__nv_bfloat162*)&kh1);
                uint32_t kl0 = CVT2(kv.x - kf0.x, kv.y - kf0.y);
                uint32_t kl1 = CVT2(kv.z - kf1.x, kv.w - kf1.y);
                uint32_t vh0 = CVT2(vv.x, vv.y), vh1 = CVT2(vv.z, vv.w);
                float2 vf0 = __bfloat1622float2(*(__nv_bfloat162*)&vh0);
                float2 vf1 = __bfloat1622float2(*(__nv_bfloat162*)&vh1);
                uint32_t vl0 = CVT2(vv.x - vf0.x, vv.y - vf0.y);
                uint32_t vl1 = CVT2(vv.z - vf1.x, vv.w - vf1.y);
                int seg = c4 >> 1;
                uint32_t sw = row * 128 + ((seg ^ (row & 7)) << 4) + (c4 & 1) * 8;
                *(uint2*)(KH + sw) = make_uint2(kh0, kh1);
                *(uint2*)(KL + sw) = make_uint2(kl0, kl1);
                *(uint2*)(VH + sw) = make_uint2(vh0, vh1);
                *(uint2*)(VL + sw) = make_uint2(vl0, vl1);
            }
            __syncthreads();

            float sc[8][4] = {};
            for (int nt2 = 0; nt2 < nt2max; nt2++) {
                int krow = nt2 * 16 + (l & 7) + ((l >> 3) & 1) * 8;
#pragma unroll
                for (int ks = 0; ks < 4; ks++) {
                    int seg = ks * 2 + (l >> 4);
                    uint32_t off = krow * 128 + ((seg ^ (krow & 7)) << 4);
                    uint32_t bh[4], bl[4];
                    LDSM4(bh, sKH + off);
                    LDSM4(bl, sKL + off);
                    MMA_BF16(sc[2 * nt2], qh[ks], bh[0], bh[2]);
                    MMA_BF16(sc[2 * nt2], qh[ks], bl[0], bl[2]);
                    MMA_BF16(sc[2 * nt2], ql[ks], bh[0], bh[2]);
                    MMA_BF16(sc[2 * nt2 + 1], qh[ks], bh[1], bh[3]);
                    MMA_BF16(sc[2 * nt2 + 1], qh[ks], bl[1], bl[3]);
                    MMA_BF16(sc[2 * nt2 + 1], ql[ks], bh[1], bh[3]);
                }
            }

            for (int j = 0; j < ntiles; j++) {
                int gk = key0 + j * 8 + 2 * (l & 3);
                if (needmask) {
                    int dA0 = gqA - gk;     if (dA0 < 0) dA0 = -dA0;
                    int dA1 = gqA - gk - 1; if (dA1 < 0) dA1 = -dA1;
                    int dB0 = gqA + 8 - gk;     if (dB0 < 0) dB0 = -dB0;
                    int dB1 = gqA + 8 - gk - 1; if (dB1 < 0) dB1 = -dB1;
                    sc[j][0] = (dA0 <= WINR) ? sc[j][0] * ASCALE : -1e30f;
                    sc[j][1] = (dA1 <= WINR) ? sc[j][1] * ASCALE : -1e30f;
                    sc[j][2] = (dB0 <= WINR) ? sc[j][2] * ASCALE : -1e30f;
                    sc[j][3] = (dB1 <= WINR) ? sc[j][3] * ASCALE : -1e30f;
                } else if (ph == 1) {
                    bool ok = (j * 8 + 2 * (l & 3)) < 32;
                    sc[j][0] = ok ? sc[j][0] * ASCALE : -1e30f;
                    sc[j][1] = ok ? sc[j][1] * ASCALE : -1e30f;
                    sc[j][2] = ok ? sc[j][2] * ASCALE : -1e30f;
                    sc[j][3] = ok ? sc[j][3] * ASCALE : -1e30f;
                } else {
                    sc[j][0] *= ASCALE; sc[j][1] *= ASCALE;
                    sc[j][2] *= ASCALE; sc[j][3] *= ASCALE;
                }
            }

            float mxA = -1e30f, mxB = -1e30f;
            for (int j = 0; j < ntiles; j++) {
                mxA = fmaxf(mxA, fmaxf(sc[j][0], sc[j][1]));
                mxB = fmaxf(mxB, fmaxf(sc[j][2], sc[j][3]));
            }
            mxA = fmaxf(mxA, __shfl_xor_sync(0xffffffffu, mxA, 1));
            mxA = fmaxf(mxA, __shfl_xor_sync(0xffffffffu, mxA, 2));
            mxB = fmaxf(mxB, __shfl_xor_sync(0xffffffffu, mxB, 1));
            mxB = fmaxf(mxB, __shfl_xor_sync(0xffffffffu, mxB, 2));
            float nmA = fmaxf(mA, mxA), nmB = fmaxf(mB, mxB);
            float fA = __expf(mA - nmA), fB = __expf(mB - nmB);
            mA = nmA; mB = nmB;
            float sA = 0.f, sB = 0.f;
            for (int j = 0; j < ntiles; j++) {
                sc[j][0] = __expf(sc[j][0] - nmA);
                sc[j][1] = __expf(sc[j][1] - nmA);
                sc[j][2] = __expf(sc[j][2] - nmB);
                sc[j][3] = __expf(sc[j][3] - nmB);
                sA += sc[j][0] + sc[j][1];
                sB += sc[j][2] + sc[j][3];
            }
            sA += __shfl_xor_sync(0xffffffffu, sA, 1);
            sA += __shfl_xor_sync(0xffffffffu, sA, 2);
            sB += __shfl_xor_sync(0xffffffffu, sB, 1);
            sB += __shfl_xor_sync(0xffffffffu, sB, 2);
            lA = lA * fA + sA;
            lB = lB * fB + sB;
#pragma unroll
            for (int j = 0; j < 8; j++) {
                acc[j][0] *= fA; acc[j][1] *= fA;
                acc[j][2] *= fB; acc[j][3] *= fB;
            }

            for (int kt = 0; kt < nt2max; kt++) {
                uint32_t ah[4], al_[4];
                ah[0] = CVT2(sc[2 * kt][0], sc[2 * kt][1]);
                ah[1] = CVT2(sc[2 * kt][2], sc[2 * kt][3]);
                ah[2] = CVT2(sc[2 * kt + 1][0], sc[2 * kt + 1][1]);
                ah[3] = CVT2(sc[2 * kt + 1][2], sc[2 * kt + 1][3]);
                {
                    float2 r0 = __bfloat1622float2(*(__nv_bfloat162*)&ah[0]);
                    float2 r1 = __bfloat1622float2(*(__nv_bfloat162*)&ah[1]);
                    float2 r2 = __bfloat1622float2(*(__nv_bfloat162*)&ah[2]);
                    float2 r3 = __bfloat1622float2(*(__nv_bfloat162*)&ah[3]);
                    al_[0] = CVT2(sc[2 * kt][0] - r0.x, sc[2 * kt][1] - r0.y);
                    al_[1] = CVT2(sc[2 * kt][2] - r1.x, sc[2 * kt][3] - r1.y);
                    al_[2] = CVT2(sc[2 * kt + 1][0] - r2.x, sc[2 * kt + 1][1] - r2.y);
                    al_[3] = CVT2(sc[2 * kt + 1][2] - r3.x, sc[2 * kt + 1][3] - r3.y);
                }
                int vrow = kt * 16 + (l & 7) + ((l >> 3) & 1) * 8;
#pragma unroll
                for (int jn2 = 0; jn2 < 4; jn2++) {
                    int seg = jn2 * 2 + (l >> 4);
                    uint32_t off = vrow * 128 + ((seg ^ (vrow & 7)) << 4);
                    uint32_t bh[4], bl[4];
                    LDSM4T(bh, sVH + off);
                    LDSM4T(bl, sVL + off);
                    MMA_BF16(acc[2 * jn2], ah, bh[0], bh[1]);
                    MMA_BF16(acc[2 * jn2], ah, bl[0], bl[1]);
                    MMA_BF16(acc[2 * jn2], al_, bh[0], bh[1]);
                    MMA_BF16(acc[2 * jn2 + 1], ah, bh[2], bh[3]);
                    MMA_BF16(acc[2 * jn2 + 1], ah, bl[2], bl[3]);
                    MMA_BF16(acc[2 * jn2 + 1], al_, bh[2], bh[3]);
                }
            }
        }

        float invA = 1.f / lA, invB = 1.f / lB;
#pragma unroll
        for (int j = 0; j < 8; j++) {
            int hd = j * 8 + 2 * (l & 3);
            size_t offA = (hbase + gqA) * 64 + hd;
            size_t offB = offA + 8 * 64;
            float2 oA = make_float2(acc[j][0] * invA, acc[j][1] * invA);
            float2 oB = make_float2(acc[j][2] * invB, acc[j][3] * invB);
            if (ph > 0) {
                float2 pA = *(float2*)&O[offA]; oA.x += pA.x; oA.y += pA.y;
                float2 pB = *(float2*)&O[offB]; oB.x += pB.x; oB.y += pB.y;
            }
            *(float2*)&O[offA] = oA;
            *(float2*)&O[offB] = oB;
        }
    }
}

// ---------------------------------------------------------------------------
// convert out_W and the 3 V weight matrices -> bf16 hi/lo.
// ---------------------------------------------------------------------------
__global__ __launch_bounds__(256) void k_cvt_w(const float* __restrict__ W,
                                               P3 Vs,
                                               __nv_bfloat16* __restrict__ Wh,
                                               __nv_bfloat16* __restrict__ Wl,
                                               __nv_bfloat16* __restrict__ Vh,
                                               __nv_bfloat16* __restrict__ Vl) {
    int bid = blockIdx.x;
    int t = threadIdx.x;
    float4 v;
    __nv_bfloat16 *Hd, *Ld;
    size_t dst;
    if (bid < 1024) {
        int idx = bid * 256 + t;
        v = *(const float4*)&W[(size_t)idx * 4];
        dst = (size_t)idx * 4;
        Hd = Wh; Ld = Wl;
    } else {
        int idx = (bid - 1024) * 256 + t;
        int p = idx >> 14, rem = idx & 16383;
        v = *(const float4*)&sel(Vs, p)[(size_t)rem * 4];
        dst = ((size_t)p << 16) + (size_t)rem * 4;
        Hd = Vh; Ld = Vl;
    }
    __nv_bfloat162 h0 = __floats2bfloat162_rn(v.x, v.y);
    __nv_bfloat162 h1 = __floats2bfloat162_rn(v.z, v.w);
    __nv_bfloat162 l0 = __floats2bfloat162_rn(v.x - __bfloat162float(h0.x),
                                              v.y - __bfloat162float(h0.y));
    __nv_bfloat162 l1 = __floats2bfloat162_rn(v.z - __bfloat162float(h1.x),
                                              v.w - __bfloat162float(h1.y));
    *(uint32_t*)&Hd[dst]     = *(uint32_t*)&h0;
    *(uint32_t*)&Hd[dst + 2] = *(uint32_t*)&h1;
    *(uint32_t*)&Ld[dst]     = *(uint32_t*)&l0;
    *(uint32_t*)&Ld[dst + 2] = *(uint32_t*)&l1;
}

// ---------------------------------------------------------------------------
// out = fused(C) @ W^T + b via mma.sync bf16x3 (R14 version, fused A split).
// ---------------------------------------------------------------------------
#define OP_LDG_A(kc)                                                           \
    do {                                                                       \
        int _hh = (kc) >> 1;                                                   \
        int _hdb = ((kc) & 1) * 32;                                            \
        _Pragma("unroll")                                                      \
        for (int rep = 0; rep < 2; rep++) {                                    \
            int idx = t + rep * 256;                                           \
            int row = idx >> 2, seg = idx & 3;                                 \
            int m = m0 + row;                                                  \
            int bi = m >> 11, ni = m & 2047;                                   \
            const float* s = &C[((size_t)(bi * 16 + _hh) * 2048 + ni) * 64     \
                                + _hdb + seg * 8];                             \
            av[rep][0] = *(const float4*)s;                                    \
            av[rep][1] = *(const float4*)(s + 4);                              \
        }                                                                      \
    } while (0)

#define OP_STS_A(s)                                                            \
    do {                                                                       \
        _Pragma("unroll")                                                      \
        for (int rep = 0; rep < 2; rep++) {                                    \
            int idx = t + rep * 256;                                           \
            int row = idx >> 2, seg = idx & 3;                                 \
            uint32_t h0 = CVT2(av[rep][0].x, av[rep][0].y);                    \
            uint32_t h1 = CVT2(av[rep][0].z, av[rep][0].w);                    \
            uint32_t h2 = CVT2(av[rep][1].x, av[rep][1].y);                    \
            uint32_t h3 = CVT2(av[rep][1].z, av[rep][1].w);                    \
            float2 f0 = __bfloat1622float2(*(__nv_bfloat162*)&h0);             \
            float2 f1 = __bfloat1622float2(*(__nv_bfloat162*)&h1);             \
            float2 f2 = __bfloat1622float2(*(__nv_bfloat162*)&h2);             \
            float2 f3 = __bfloat1622float2(*(__nv_bfloat162*)&h3);             \
            uint32_t l0 = CVT2(av[rep][0].x - f0.x, av[rep][0].y - f0.y);      \
            uint32_t l1 = CVT2(av[rep][0].z - f1.x, av[rep][0].w - f1.y);      \
            uint32_t l2 = CVT2(av[rep][1].x - f2.x, av[rep][1].y - f2.y);      \
            uint32_t l3 = CVT2(av[rep][1].z - f3.x, av[rep][1].w - f3.y);      \
            uint32_t off = (s) * 40960 + row * 80 + seg * 16;                  \
            *(uint4*)(smc + off)         = make_uint4(h0, h1, h2, h3);         \
            *(uint4*)(smc + 10240 + off) = make_uint4(l0, l1, l2, l3);         \
        }                                                                      \
    } while (0)

#define OP_LOAD_W(kc, s)                                                       \
    do {                                                                       \
        uint32_t _base = sb + (s) * 40960 + 20480;                             \
        _Pragma("unroll")                                                      \
        for (int rep = 0; rep < 4; rep++) {                                    \
            int idx = t + rep * 256;                                           \
            int plane = idx >> 9;                                              \
            int rem = idx & 511;                                               \
            int row = rem >> 2, seg = rem & 3;                                 \
            uint32_t dst = _base + plane * 10240 + row * 80 + seg * 16;        \
            const __nv_bfloat16* src = plane ? Wlg : Whg;                      \
            CP_ASYNC16(dst, &src[(size_t)(n0 + row) * 1024 + (kc) * 32 + seg * 8]); \
        }                                                                      \
    } while (0)

__global__ __launch_bounds__(256, 2) void k_outproj_mma(const float* __restrict__ C,
                                                        const __nv_bfloat16* __restrict__ Whg,
                                                        const __nv_bfloat16* __restrict__ Wlg,
                                                        const float* __restrict__ bias,
                                                        float* __restrict__ out) {
    extern __shared__ char smc[];
    uint32_t sb = smem_u32(smc);
    int t = threadIdx.x;
    int wid = t >> 5, l = t & 31;
    int wm = wid & 3, wn = wid >> 2;
    int m0 = blockIdx.x * 128, n0 = blockIdx.y * 128;

    float acc[2][8][4] = {};
    float4 av[2][2];

    int row_a = wm * 32 + (l & 15);
    int sega  = (l >> 4);
    int row_b = wn * 64 + ((l >> 4) & 1) * 8 + (l & 7);
    int segb  = ((l >> 3) & 1);

    OP_LDG_A(0);
    OP_LOAD_W(0, 0);
    CP_COMMIT();

    for (int kc = 0; kc < 32; kc++) {
        OP_STS_A(kc & 1);
        if (kc + 1 < 32) {
            OP_LOAD_W(kc + 1, (kc + 1) & 1);
            CP_COMMIT();
            OP_LDG_A(kc + 1);
            CP_WAIT(1);
        } else {
            CP_WAIT(0);
        }
        __syncthreads();
        uint32_t base = sb + (kc & 1) * 40960;

#pragma unroll
        for (int ks = 0; ks < 2; ks++) {
            uint32_t ah[2][4], al_[2][4];
#pragma unroll
            for (int mt = 0; mt < 2; mt++) {
                int ra = row_a + mt * 16;
                uint32_t off = ra * 80 + (ks * 2 + sega) * 16;
                LDSM4(ah[mt], base + off);
                LDSM4(al_[mt], base + 10240 + off);
            }
#pragma unroll
            for (int ntp = 0; ntp < 4; ntp++) {
                int rb = row_b + ntp * 16;
                uint32_t off = rb * 80 + (ks * 2 + segb) * 16;
                uint32_t bh[4], bl[4];
                LDSM4(bh, base + 20480 + off);
                LDSM4(bl, base + 30720 + off);
#pragma unroll
                for (int mt = 0; mt < 2; mt++) {
#pragma unroll
                    for (int half = 0; half < 2; half++) {
                        float* d = acc[mt][ntp * 2 + half];
                        MMA_BF16(d, ah[mt], bh[half * 2], bh[half * 2 + 1]);
                        MMA_BF16(d, ah[mt], bl[half * 2], bl[half * 2 + 1]);
                        MMA_BF16(d, al_[mt], bh[half * 2], bh[half * 2 + 1]);
                    }
                }
            }
        }
        __syncthreads();
    }

#pragma unroll
    for (int mt = 0; mt < 2; mt++) {
        int r0 = m0 + wm * 32 + mt * 16 + (l >> 2);
#pragma unroll
        for (int nt = 0; nt < 8; nt++) {
            int c = n0 + wn * 64 + nt * 8 + 2 * (l & 3);
            float b0 = bias[c], b1 = bias[c + 1];
            float* d = acc[mt][nt];
            *(float2*)&out[(size_t)r0 * 1024 + c] = make_float2(d[0] + b0, d[1] + b1);
            *(float2*)&out[(size_t)(r0 + 8) * 1024 + c] = make_float2(d[2] + b0, d[3] + b1);
        }
    }
}

// ---------------------------------------------------------------------------
__global__ __launch_bounds__(128) void k_heads(const float* __restrict__ C,
                                               const float* __restrict__ tW, const float* __restrict__ tb,
                                               const float* __restrict__ iW, const float* __restrict__ ib,
                                               const float* __restrict__ cW, const float* __restrict__ cb,
                                               float* __restrict__ out) {
    int r = blockIdx.x;
    int b = r >> 11, n = r & 2047;
    __shared__ float last[64];
    int t = threadIdx.x;
    if (t < 64) last[t] = C[((size_t)(b * 16) * 2048 + n) * 64 + t];
    __syncthreads();
    if (t < 2) {
        float s = tb[t];
        for (int k = 0; k < 64; k++) s += last[k] * tW[t * 64 + k];
        out[4194304 + (size_t)r * 2 + t] = s;
    } else if (t < 66) {
        int j = t - 2;
        float s = ib[j];
        for (int k = 0; k < 64; k++) s += last[k] * iW[j * 64 + k];
        out[4202496 + (size_t)r * 64 + j] = s;
    } else if (t < 98) {
        int j = t - 66;
        float s = cb[j];
        for (int k = 0; k < 64; k++) s += last[k] * cW[j * 64 + k];
        out[4464640 + (size_t)r * 32 + j] = s;
    }
}

// ---------------------------------------------------------------------------
extern "C" void kernel_launch(void* const* d_in, const int* in_sizes, int n_in,
                              void* d_out, int out_size) {
    const float* x   = (const float*)d_in[0];
    const float* mem = (const float*)d_in[1];
    P3 Us  = { (const float*)d_in[2],  (const float*)d_in[8],  (const float*)d_in[14] };
    P3 Vs  = { (const float*)d_in[3],  (const float*)d_in[9],  (const float*)d_in[15] };
    P3 als = { (const float*)d_in[4],  (const float*)d_in[10], (const float*)d_in[16] };
    P3 As  = { (const float*)d_in[5],  (const float*)d_in[11], (const float*)d_in[17] };
    P3 Bls = { (const float*)d_in[6],  (const float*)d_in[12], (const float*)d_in[18] };
    P3 bis = { (const float*)d_in[7],  (const float*)d_in[13], (const float*)d_in[19] };
    const float* outW = (const float*)d_in[20];
    const float* outb = (const float*)d_in[21];
    const float* tW = (const float*)d_in[22];
    const float* tb = (const float*)d_in[23];
    const float* iW = (const float*)d_in[24];
    const float* ib = (const float*)d_in[25];
    const float* cW = (const float*)d_in[26];
    const float* cb = (const float*)d_in[27];
    float* out = (float*)d_out;

    void *pL, *pQKV, *pC, *pTh, *pTl, *pVh, *pVl, *pWh, *pWl;
    cudaGetSymbolAddress(&pL, g_l);
    cudaGetSymbolAddress(&pQKV, g_qkv);
    cudaGetSymbolAddress(&pC, g_comb);
    cudaGetSymbolAddress(&pTh, g_th);
    cudaGetSymbolAddress(&pTl, g_tl);
    cudaGetSymbolAddress(&pVh, g_vh);
    cudaGetSymbolAddress(&pVl, g_vl);
    cudaGetSymbolAddress(&pWh, g_wh);
    cudaGetSymbolAddress(&pWl, g_wl);
    float* Lb = (float*)pL;
    float* QKV = (float*)pQKV;
    float* Cb = (float*)pC;
    const size_t QSZ = (size_t)BATCH * NHEAD * NSEQ * 64;

    k_xu<<<dim3(64, 3), 128>>>(x, Us, als, As,
                               (__nv_bfloat16*)pTh, (__nv_bfloat16*)pTl, Lb);
    k_cvt_w<<<1216, 256>>>(outW, Vs,
                           (__nv_bfloat16*)pWh, (__nv_bfloat16*)pWl,
                           (__nv_bfloat16*)pVh, (__nv_bfloat16*)pVl);

    const int SMEM_PJ = 75776;
    cudaFuncSetAttribute(k_proj_mma, cudaFuncAttributeMaxDynamicSharedMemorySize, SMEM_PJ);
    k_proj_mma<<<dim3(32, 8, 3), 256, SMEM_PJ>>>((const __nv_bfloat16*)pTh,
                                                 (const __nv_bfloat16*)pTl,
                                                 (const __nv_bfloat16*)pVh,
                                                 (const __nv_bfloat16*)pVl,
                                                 Lb, Bls, bis, QKV);

    const int SMEM_ATTN = 32768;
    cudaFuncSetAttribute(k_attn_mma, cudaFuncAttributeMaxDynamicSharedMemorySize, SMEM_ATTN);
    k_attn_mma<<<dim3(32, 16, 2), 128, SMEM_ATTN>>>(QKV, QKV + QSZ, QKV + 2 * QSZ, mem, Cb);

    const int SMEM_OP = 81920;
    cudaFuncSetAttribute(k_outproj_mma, cudaFuncAttributeMaxDynamicSharedMemorySize, SMEM_OP);
    k_outproj_mma<<<dim3(32, 8), 256, SMEM_OP>>>(Cb,
                                                 (const __nv_bfloat16*)pWh,
                                                 (const __nv_bfloat16*)pWl,
                                                 outb, out);

    k_heads<<<4096, 128>>>(Cb, tW, tb, iW, ib, cW, cb, out);
}

// round 17
// speedup vs baseline: 1.1266x; 1.0320x over previous
#include <cuda_runtime.h>
#include <cuda_bf16.h>
#include <math.h>
#include <stdint.h>

#define NSEQ 2048
#define BATCH 2
#define NHEAD 16
#define MROWS 4096
#define WINR 128
#define ASCALE 0.125f

typedef unsigned long long u64;
struct P3 { const float* a; const float* b; const float* c; };
__device__ __forceinline__ const float* sel(P3 p, int i) {
    return i == 0 ? p.a : (i == 1 ? p.b : p.c);
}

__device__ __forceinline__ uint32_t smem_u32(const void* p) {
    uint32_t a;
    asm("{ .reg .u64 t; cvta.to.shared.u64 t, %1; cvt.u32.u64 %0, t; }" : "=r"(a) : "l"(p));
    return a;
}

// ---- portable tensor-core + async-copy ops (sm_80+ baseline PTX) ----
__device__ __forceinline__ void MMA_BF16(float* d, const uint32_t* a, uint32_t b0, uint32_t b1) {
    asm volatile(
        "mma.sync.aligned.m16n8k16.row.col.f32.bf16.bf16.f32 "
        "{%0,%1,%2,%3}, {%4,%5,%6,%7}, {%8,%9}, {%0,%1,%2,%3};"
        : "+f"(d[0]), "+f"(d[1]), "+f"(d[2]), "+f"(d[3])
        : "r"(a[0]), "r"(a[1]), "r"(a[2]), "r"(a[3]), "r"(b0), "r"(b1));
}
__device__ __forceinline__ void LDSM4(uint32_t* r, uint32_t addr) {
    asm volatile("ldmatrix.sync.aligned.m8n8.x4.shared.b16 {%0,%1,%2,%3}, [%4];"
                 : "=r"(r[0]), "=r"(r[1]), "=r"(r[2]), "=r"(r[3]) : "r"(addr));
}
__device__ __forceinline__ void LDSM4T(uint32_t* r, uint32_t addr) {
    asm volatile("ldmatrix.sync.aligned.m8n8.x4.trans.shared.b16 {%0,%1,%2,%3}, [%4];"
                 : "=r"(r[0]), "=r"(r[1]), "=r"(r[2]), "=r"(r[3]) : "r"(addr));
}
__device__ __forceinline__ uint32_t CVT2(float lo, float hi) {
    uint32_t r; asm("cvt.rn.bf16x2.f32 %0, %1, %2;" : "=r"(r) : "f"(hi), "f"(lo)); return r;
}
#define CP_ASYNC16(dst, src) \
    asm volatile("cp.async.ca.shared.global [%0], [%1], 16;" :: "r"(dst), "l"(src) : "memory")
#define CP_COMMIT() asm volatile("cp.async.commit_group;" ::: "memory")
#define CP_WAIT(n)  asm volatile("cp.async.wait_group %0;" :: "n"(n) : "memory")

// ---------------- scratch ----------------
__device__ float g_l[3 * MROWS * 4];
__device__ float g_qkv[3 * BATCH * NHEAD * NSEQ * 64];
__device__ float g_comb[BATCH * NHEAD * NSEQ * 64];
__device__ __nv_bfloat16 g_xh[MROWS * 1024];
__device__ __nv_bfloat16 g_xl[MROWS * 1024];
__device__ __nv_bfloat16 g_uth[3 * 64 * 1024];
__device__ __nv_bfloat16 g_utl[3 * 64 * 1024];
__device__ __nv_bfloat16 g_th[3 * MROWS * 64];
__device__ __nv_bfloat16 g_tl[3 * MROWS * 64];
__device__ __nv_bfloat16 g_vh[3 * 1024 * 64];
__device__ __nv_bfloat16 g_vl[3 * 1024 * 64];
__device__ __nv_bfloat16 g_wh[1024 * 1024];
__device__ __nv_bfloat16 g_wl[1024 * 1024];

// ---------------------------------------------------------------------------
// split x -> planar bf16 hi/lo.  4096 blocks x 256 thr, 1 float4/thread.
// ---------------------------------------------------------------------------
__global__ __launch_bounds__(256) void k_cvt_x(const float* __restrict__ X,
                                               __nv_bfloat16* __restrict__ Xh,
                                               __nv_bfloat16* __restrict__ Xl) {
    size_t idx = (size_t)blockIdx.x * 256 + threadIdx.x;   // over 1M float4
    float4 v = *(const float4*)&X[idx * 4];
    __nv_bfloat162 h0 = __floats2bfloat162_rn(v.x, v.y);
    __nv_bfloat162 h1 = __floats2bfloat162_rn(v.z, v.w);
    __nv_bfloat162 l0 = __floats2bfloat162_rn(v.x - __bfloat162float(h0.x),
                                              v.y - __bfloat162float(h0.y));
    __nv_bfloat162 l1 = __floats2bfloat162_rn(v.z - __bfloat162float(h1.x),
                                              v.w - __bfloat162float(h1.y));
    *(uint32_t*)&Xh[idx * 4]     = *(uint32_t*)&h0;
    *(uint32_t*)&Xh[idx * 4 + 2] = *(uint32_t*)&h1;
    *(uint32_t*)&Xl[idx * 4]     = *(uint32_t*)&l0;
    *(uint32_t*)&Xl[idx * 4 + 2] = *(uint32_t*)&l1;
}

// ---------------------------------------------------------------------------
// l = x @ A (12 cols fused).  (R15 verbatim)
// ---------------------------------------------------------------------------
__global__ __launch_bounds__(128) void k_lora(const float* __restrict__ X,
                                              P3 As, float* __restrict__ Lb) {
    int m = blockIdx.x;
    int t = threadIdx.x;
    float p[12] = {};
    const float* A0 = As.a; const float* A1 = As.b; const float* A2 = As.c;
    for (int k = t; k < 1024; k += 128) {
        float xv = X[(size_t)m * 1024 + k];
#pragma unroll
        for (int j = 0; j < 4; j++) {
            p[j]     += xv * A0[k * 4 + j];
            p[4 + j] += xv * A1[k * 4 + j];
            p[8 + j] += xv * A2[k * 4 + j];
        }
    }
    __shared__ float red[12][128];
#pragma unroll
    for (int j = 0; j < 12; j++) red[j][t] = p[j];
    __syncthreads();
    for (int s = 64; s > 0; s >>= 1) {
        if (t < s) {
#pragma unroll
            for (int j = 0; j < 12; j++) red[j][t] += red[j][t + s];
        }
        __syncthreads();
    }
    if (t < 12) {
        int pr = t >> 2, j = t & 3;
        Lb[(size_t)pr * MROWS * 4 + (size_t)m * 4 + j] = red[t][0];
    }
}

// ---------------------------------------------------------------------------
// convert out_W, V matrices, and U^T -> bf16 hi/lo.
// blocks [0,1024): W.  [1024,1216): V.  [1216,1984): U transpose-split.
// ---------------------------------------------------------------------------
__global__ __launch_bounds__(256) void k_cvt_w(const float* __restrict__ W,
                                               P3 Vs, P3 Us,
                                               __nv_bfloat16* __restrict__ Wh,
                                               __nv_bfloat16* __restrict__ Wl,
                                               __nv_bfloat16* __restrict__ Vh,
                                               __nv_bfloat16* __restrict__ Vl,
                                               __nv_bfloat16* __restrict__ Uth,
                                               __nv_bfloat16* __restrict__ Utl) {
    int bid = blockIdx.x;
    int t = threadIdx.x;
    if (bid >= 1216) {                       // U branch: scalar transpose-split
        int idx = (bid - 1216) * 256 + t;    // over 3*65536
        int p = idx >> 16, rem = idx & 65535;
        int k = rem >> 6, n = rem & 63;
        float v = sel(Us, p)[(size_t)k * 64 + n];
        __nv_bfloat16 h = __float2bfloat16_rn(v);
        __nv_bfloat16 l = __float2bfloat16_rn(v - __bfloat162float(h));
        size_t dst = ((size_t)p << 16) + (size_t)n * 1024 + k;
        Uth[dst] = h;
        Utl[dst] = l;
        return;
    }
    float4 v;
    __nv_bfloat16 *Hd, *Ld;
    size_t dst;
    if (bid < 1024) {
        int idx = bid * 256 + t;
        v = *(const float4*)&W[(size_t)idx * 4];
        dst = (size_t)idx * 4;
        Hd = Wh; Ld = Wl;
    } else {
        int idx = (bid - 1024) * 256 + t;
        int p = idx >> 14, rem = idx & 16383;
        v = *(const float4*)&sel(Vs, p)[(size_t)rem * 4];
        dst = ((size_t)p << 16) + (size_t)rem * 4;
        Hd = Vh; Ld = Vl;
    }
    __nv_bfloat162 h0 = __floats2bfloat162_rn(v.x, v.y);
    __nv_bfloat162 h1 = __floats2bfloat162_rn(v.z, v.w);
    __nv_bfloat162 l0 = __floats2bfloat162_rn(v.x - __bfloat162float(h0.x),
                                              v.y - __bfloat162float(h0.y));
    __nv_bfloat162 l1 = __floats2bfloat162_rn(v.z - __bfloat162float(h1.x),
                                              v.w - __bfloat162float(h1.y));
    *(uint32_t*)&Hd[dst]     = *(uint32_t*)&h0;
    *(uint32_t*)&Hd[dst + 2] = *(uint32_t*)&h1;
    *(uint32_t*)&Ld[dst]     = *(uint32_t*)&l0;
    *(uint32_t*)&Ld[dst + 2] = *(uint32_t*)&l1;
}

// ---------------------------------------------------------------------------
// T = (x @ U) * alpha via mma.sync bf16x3 -> bf16 hi/lo planes.
// CTA 128m x 64n, Kc=32, 2-stage cp.async.  grid (32, 3).
// smem stage: Xh+0 (10240), Xl+10240, Uh+20480 (5120), Ul+25600.  stage=30720B.
// ---------------------------------------------------------------------------
#define XU_LOAD(kc, s)                                                          \
    do {                                                                        \
        uint32_t _base = sb + (s) * 30720;                                      \
        _Pragma("unroll")                                                       \
        for (int rep = 0; rep < 6; rep++) {                                     \
            int idx = t + rep * 256;                                            \
            uint32_t dst;                                                       \
            const __nv_bfloat16* src;                                           \
            size_t g;                                                           \
            if (idx < 1024) {                                                   \
                int plane = idx >> 9, rem = idx & 511;                          \
                int row = rem >> 2, seg = rem & 3;                              \
                dst = _base + plane * 10240 + row * 80 + seg * 16;              \
                src = plane ? Xlg : Xhg;                                        \
                g = (size_t)(m0 + row) * 1024 + (kc) * 32 + seg * 8;            \
            } else {                                                            \
                int q = idx - 1024;                                             \
                int plane = q >> 8, rem = q & 255;                              \
                int row = rem >> 2, seg = rem & 3;                              \
                dst = _base + 20480 + plane * 5120 + row * 80 + seg * 16;       \
                src = plane ? Utl : Uth;                                        \
                g = (size_t)row * 1024 + (kc) * 32 + seg * 8;                   \
            }                                                                   \
            CP_ASYNC16(dst, &src[g]);                                           \
        }                                                                       \
    } while (0)

__global__ __launch_bounds__(256, 2) void k_xu_mma(const __nv_bfloat16* __restrict__ Xhg,
                                                   const __nv_bfloat16* __restrict__ Xlg,
                                                   const __nv_bfloat16* __restrict__ Uthg,
                                                   const __nv_bfloat16* __restrict__ Utlg,
                                                   P3 als,
                                                   __nv_bfloat16* __restrict__ TH,
                                                   __nv_bfloat16* __restrict__ TL) {
    extern __shared__ char smx[];
    uint32_t sb = smem_u32(smx);
    int p = blockIdx.y;
    const __nv_bfloat16* Uth = Uthg + ((size_t)p << 16);
    const __nv_bfloat16* Utl = Utlg + ((size_t)p << 16);
    const float* alpha = sel(als, p);
    __nv_bfloat16* Th = TH + (size_t)p * MROWS * 64;
    __nv_bfloat16* Tl = TL + (size_t)p * MROWS * 64;

    int t = threadIdx.x;
    int wid = t >> 5, l = t & 31;
    int wm = wid & 3, wn = wid >> 2;
    int m0 = blockIdx.x * 128;

    float acc[2][4][4] = {};
    int row_a = wm * 32 + (l & 15);
    int sega  = (l >> 4);
    int row_b = wn * 32 + ((l >> 4) & 1) * 8 + (l & 7);
    int segb  = ((l >> 3) & 1);

    XU_LOAD(0, 0);
    CP_COMMIT();

    for (int kc = 0; kc < 32; kc++) {
        if (kc + 1 < 32) {
            XU_LOAD(kc + 1, (kc + 1) & 1);
            CP_COMMIT();
            CP_WAIT(1);
        } else {
            CP_WAIT(0);
        }
        __syncthreads();
        uint32_t base = sb + (kc & 1) * 30720;

#pragma unroll
        for (int ks = 0; ks < 2; ks++) {
            uint32_t ah[2][4], al_[2][4];
#pragma unroll
            for (int mt = 0; mt < 2; mt++) {
                int ra = row_a + mt * 16;
                uint32_t off = ra * 80 + (ks * 2 + sega) * 16;
                LDSM4(ah[mt], base + off);
                LDSM4(al_[mt], base + 10240 + off);
            }
#pragma unroll
            for (int ntp = 0; ntp < 2; ntp++) {
                int rb = row_b + ntp * 16;
                uint32_t off = rb * 80 + (ks * 2 + segb) * 16;
                uint32_t bh[4], bl[4];
                LDSM4(bh, base + 20480 + off);
                LDSM4(bl, base + 25600 + off);
#pragma unroll
                for (int mt = 0; mt < 2; mt++) {
#pragma unroll
                    for (int half = 0; half < 2; half++) {
                        float* d = acc[mt][ntp * 2 + half];
                        MMA_BF16(d, ah[mt], bh[half * 2], bh[half * 2 + 1]);
                        MMA_BF16(d, ah[mt], bl[half * 2], bl[half * 2 + 1]);
                        MMA_BF16(d, al_[mt], bh[half * 2], bh[half * 2 + 1]);
                    }
                }
            }
        }
        __syncthreads();
    }

    // epilogue: * alpha, split hi/lo, store planes
#pragma unroll
    for (int nt = 0; nt < 4; nt++) {
        int c = wn * 32 + nt * 8 + 2 * (l & 3);
        float a0 = alpha[c], a1 = alpha[c + 1];
#pragma unroll
        for (int mt = 0; mt < 2; mt++) {
            int r0 = m0 + wm * 32 + mt * 16 + (l >> 2);
            float* d = acc[mt][nt];
            float v0 = d[0] * a0, v1 = d[1] * a1;
            float v2 = d[2] * a0, v3 = d[3] * a1;
            uint32_t h0 = CVT2(v0, v1);
            float2 f0 = __bfloat1622float2(*(__nv_bfloat162*)&h0);
            uint32_t l0 = CVT2(v0 - f0.x, v1 - f0.y);
            uint32_t h1 = CVT2(v2, v3);
            float2 f1 = __bfloat1622float2(*(__nv_bfloat162*)&h1);
            uint32_t l1 = CVT2(v2 - f1.x, v3 - f1.y);
            *(uint32_t*)&Th[(size_t)r0 * 64 + c] = h0;
            *(uint32_t*)&Tl[(size_t)r0 * 64 + c] = l0;
            *(uint32_t*)&Th[(size_t)(r0 + 8) * 64 + c] = h1;
            *(uint32_t*)&Tl[(size_t)(r0 + 8) * 64 + c] = l1;
        }
    }
}

// ---------------------------------------------------------------------------
// proj via mma.sync bf16x3: out = T @ V^T (K=64) + l@B (fp32 epi) + bias.
// ---------------------------------------------------------------------------
__global__ __launch_bounds__(256, 2) void k_proj_mma(const __nv_bfloat16* __restrict__ THg,
                                                     const __nv_bfloat16* __restrict__ TLg,
                                                     const __nv_bfloat16* __restrict__ VHg,
                                                     const __nv_bfloat16* __restrict__ VLg,
                                                     const float* __restrict__ Lb,
                                                     P3 Bls, P3 bis,
                                                     float* __restrict__ QKV) {
    extern __shared__ char smp[];
    uint32_t sb = smem_u32(smp);
    const int TH = 0, TL = 18432, VH = 36864, VL = 55296, BLS = 73728;
    float* blS = (float*)(smp + BLS);
    int p = blockIdx.z;
    const __nv_bfloat16* Tph = THg + (size_t)p * MROWS * 64;
    const __nv_bfloat16* Tpl = TLg + (size_t)p * MROWS * 64;
    const __nv_bfloat16* Vph = VHg + (size_t)p * 1024 * 64;
    const __nv_bfloat16* Vpl = VLg + (size_t)p * 1024 * 64;
    const float* L = Lb + (size_t)p * MROWS * 4;
    const float* Blora = sel(Bls, p);
    const float* bias = sel(bis, p);
    float* O = QKV + (size_t)p * BATCH * NHEAD * NSEQ * 64;

    int t = threadIdx.x;
    int wid = t >> 5, l = t & 31;
    int wm = wid & 3, wn = wid >> 2;
    int m0 = blockIdx.x * 128, n0 = blockIdx.y * 128;

#pragma unroll
    for (int rep = 0; rep < 16; rep++) {
        int idx = t + rep * 256;
        int plane = idx >> 10;
        int rem = idx & 1023;
        int row = rem >> 3, seg = rem & 7;
        uint32_t dst = sb + plane * 18432 + row * 144 + seg * 16;
        const __nv_bfloat16* src;
        size_t g;
        if (plane == 0)      { src = Tph; g = (size_t)(m0 + row) * 64; }
        else if (plane == 1) { src = Tpl; g = (size_t)(m0 + row) * 64; }
        else if (plane == 2) { src = Vph; g = (size_t)(n0 + row) * 64; }
        else                 { src = Vpl; g = (size_t)(n0 + row) * 64; }
        CP_ASYNC16(dst, &src[g + seg * 8]);
    }
    if (t < 128) {
#pragma unroll
        for (int j = 0; j < 4; j++)
            blS[j * 128 + t] = Blora[(size_t)j * 1024 + n0 + t];
    }
    CP_COMMIT();
    CP_WAIT(0);
    __syncthreads();

    float acc[2][8][4] = {};
    int row_a = wm * 32 + (l & 15);
    int sega  = (l >> 4);
    int row_b = wn * 64 + ((l >> 4) & 1) * 8 + (l & 7);
    int segb  = ((l >> 3) & 1);

#pragma unroll
    for (int ks = 0; ks < 4; ks++) {
        uint32_t ah[2][4], al_[2][4];
#pragma unroll
        for (int mt = 0; mt < 2; mt++) {
            int ra = row_a + mt * 16;
            uint32_t off = ra * 144 + (ks * 2 + sega) * 16;
            LDSM4(ah[mt], sb + TH + off);
            LDSM4(al_[mt], sb + TL + off);
        }
#pragma unroll
        for (int ntp = 0; ntp < 4; ntp++) {
            int rb = row_b + ntp * 16;
            uint32_t off = rb * 144 + (ks * 2 + segb) * 16;
            uint32_t bh[4], bl[4];
            LDSM4(bh, sb + VH + off);
            LDSM4(bl, sb + VL + off);
#pragma unroll
            for (int mt = 0; mt < 2; mt++) {
#pragma unroll
                for (int half = 0; half < 2; half++) {
                    float* d = acc[mt][ntp * 2 + half];
                    MMA_BF16(d, ah[mt], bh[half * 2], bh[half * 2 + 1]);
                    MMA_BF16(d, ah[mt], bl[half * 2], bl[half * 2 + 1]);
                    MMA_BF16(d, al_[mt], bh[half * 2], bh[half * 2 + 1]);
                }
            }
        }
    }

#pragma unroll
    for (int mt = 0; mt < 2; mt++) {
        int r0 = m0 + wm * 32 + mt * 16 + (l >> 2);
        int r1 = r0 + 8;
        float lv0[4], lv1[4];
#pragma unroll
        for (int j = 0; j < 4; j++) {
            lv0[j] = L[(size_t)r0 * 4 + j];
            lv1[j] = L[(size_t)r1 * 4 + j];
        }
#pragma unroll
        for (int nt = 0; nt < 8; nt++) {
            int c = n0 + wn * 64 + nt * 8 + 2 * (l & 3);
            int cl = c - n0;
            float b0 = bias[c], b1 = bias[c + 1];
            float l00 = 0.f, l01 = 0.f, l10 = 0.f, l11 = 0.f;
#pragma unroll
            for (int j = 0; j < 4; j++) {
                float B0 = blS[j * 128 + cl], B1 = blS[j * 128 + cl + 1];
                l00 += lv0[j] * B0; l01 += lv0[j] * B1;
                l10 += lv1[j] * B0; l11 += lv1[j] * B1;
            }
            float* d = acc[mt][nt];
            int h = c >> 6, hd = c & 63;
            size_t o0 = ((size_t)((r0 >> 11) * 16 + h) * 2048 + (r0 & 2047)) * 64 + hd;
            size_t o1 = ((size_t)((r1 >> 11) * 16 + h) * 2048 + (r1 & 2047)) * 64 + hd;
            *(float2*)&O[o0] = make_float2(d[0] + l00 + b0, d[1] + l01 + b1);
            *(float2*)&O[o1] = make_float2(d[2] + l10 + b0, d[3] + l11 + b1);
        }
    }
}

// ---------------------------------------------------------------------------
// fused 3-branch flash attention via mma.sync bf16x3 (R7/R10 verbatim).
// ---------------------------------------------------------------------------
__global__ __launch_bounds__(128) void k_attn_mma(const float* __restrict__ Q,
                                                  const float* __restrict__ K,
                                                  const float* __restrict__ V,
                                                  const float* __restrict__ MEMV,
                                                  float* __restrict__ O) {
    extern __shared__ char sma[];
    char* KH = sma;
    char* KL = sma + 8192;
    char* VH = sma + 16384;
    char* VL = sma + 24576;
    uint32_t sKH = smem_u32(KH), sKL = smem_u32(KL);
    uint32_t sVH = smem_u32(VH), sVL = smem_u32(VL);

    int t = threadIdx.x;
    int w = t >> 5, l = t & 31;
    int qt = blockIdx.x, h = blockIdx.y, b = blockIdx.z;
    int q0 = qt * 64;
    size_t hbase = (size_t)(b * 16 + h) * 2048;

#pragma unroll
    for (int rep = 0; rep < 8; rep++) {
        int idx = t + rep * 128;
        int row = idx >> 4, c4 = idx & 15;
        float4 v = *(const float4*)&Q[(hbase + q0 + row) * 64 + c4 * 4];
        uint32_t h0 = CVT2(v.x, v.y), h1 = CVT2(v.z, v.w);
        float2 f0 = __bfloat1622float2(*(__nv_bfloat162*)&h0);
        float2 f1 = __bfloat1622float2(*(__nv_bfloat162*)&h1);
        uint32_t l0 = CVT2(v.x - f0.x, v.y - f0.y);
        uint32_t l1 = CVT2(v.z - f1.x, v.w - f1.y);
        int seg = c4 >> 1;
        uint32_t sw = row * 128 + ((seg ^ (row & 7)) << 4) + (c4 & 1) * 8;
        *(uint2*)(KH + sw) = make_uint2(h0, h1);
        *(uint2*)(KL + sw) = make_uint2(l0, l1);
    }
    __syncthreads();

    uint32_t qh[4][4], ql[4][4];
    {
        int qrow = w * 16 + (l & 7) + ((l >> 3) & 1) * 8;
#pragma unroll
        for (int ks = 0; ks < 4; ks++) {
            int seg = ks * 2 + (l >> 4);
            uint32_t off = qrow * 128 + ((seg ^ (qrow & 7)) << 4);
            LDSM4(qh[ks], sKH + off);
            LDSM4(ql[ks], sKL + off);
        }
    }

    int gqA = q0 + w * 16 + (l >> 2);

    for (int ph = 0; ph < 3; ph++) {
        float acc[8][4] = {};
        float mA = -1e30f, mB = -1e30f, lA = 0.f, lB = 0.f;
        int c_lo, c_hi;
        if (ph == 0) { c_lo = qt < 2 ? 2 - qt : 0; c_hi = 33 - qt; if (c_hi > 4) c_hi = 4; }
        else { c_lo = 0; c_hi = (ph == 1) ? 0 : 3; }
        int ntiles = (ph == 1) ? 4 : 8;
        int nt2max = ntiles >> 1;
        const float* Ksrc = (ph == 2) ? MEMV : K;
        const float* Vsrc = (ph == 2) ? MEMV : V;

        for (int c = c_lo; c <= c_hi; c++) {
            int key0 = (ph == 0) ? q0 - 128 + c * 64 : c * 64;
            bool needmask = (ph == 0) && (c != 2);
            __syncthreads();
#pragma unroll
            for (int rep = 0; rep < 8; rep++) {
                int idx = t + rep * 128;
                int row = idx >> 4, c4 = idx & 15;
                bool valid = (ph != 1) || (row < 32);
                size_t rowoff;
                if (ph == 2) rowoff = ((size_t)b * 256 + key0 + row) * 64;
                else if (ph == 1) rowoff = (hbase + (valid ? row * 64 : 0)) * 64;
                else rowoff = (hbase + key0 + row) * 64;
                float4 kv = valid ? *(const float4*)&Ksrc[rowoff + c4 * 4] : make_float4(0, 0, 0, 0);
                float4 vv = valid ? *(const float4*)&Vsrc[rowoff + c4 * 4] : make_float4(0, 0, 0, 0);
                uint32_t kh0 = CVT2(kv.x, kv.y), kh1 = CVT2(kv.z, kv.w);
                float2 kf0 = __bfloat1622float2(*(__nv_bfloat162*)&kh0);
                float2 kf1 = __bfloat1622float2(*(__nv_bfloat162*)&kh1);
                uint32_t kl0 = CVT2(kv.x - kf0.x, kv.y - kf0.y);
                uint32_t kl1 = CVT2(kv.z - kf1.x, kv.w - kf1.y);
                uint32_t vh0 = CVT2(vv.x, vv.y), vh1 = CVT2(vv.z, vv.w);
                float2 vf0 = __bfloat1622float2(*(__nv_bfloat162*)&vh0);
                float2 vf1 = __bfloat1622float2(*(__nv_bfloat162*)&vh1);
                uint32_t vl0 = CVT2(vv.x - vf0.x, vv.y - vf0.y);
                uint32_t vl1 = CVT2(vv.z - vf1.x, vv.w - vf1.y);
                int seg = c4 >> 1;
                uint32_t sw = row * 128 + ((seg ^ (row & 7)) << 4) + (c4 & 1) * 8;
                *(uint2*)(KH + sw) = make_uint2(kh0, kh1);
                *(uint2*)(KL + sw) = make_uint2(kl0, kl1);
                *(uint2*)(VH + sw) = make_uint2(vh0, vh1);
                *(uint2*)(VL + sw) = make_uint2(vl0, vl1);
            }
            __syncthreads();

            float sc[8][4] = {};
            for (int nt2 = 0; nt2 < nt2max; nt2++) {
                int krow = nt2 * 16 + (l & 7) + ((l >> 3) & 1) * 8;
#pragma unroll
                for (int ks = 0; ks < 4; ks++) {
                    int seg = ks * 2 + (l >> 4);
                    uint32_t off = krow * 128 + ((seg ^ (krow & 7)) << 4);
                    uint32_t bh[4], bl[4];
                    LDSM4(bh, sKH + off);
                    LDSM4(bl, sKL + off);
                    MMA_BF16(sc[2 * nt2], qh[ks], bh[0], bh[2]);
                    MMA_BF16(sc[2 * nt2], qh[ks], bl[0], bl[2]);
                    MMA_BF16(sc[2 * nt2], ql[ks], bh[0], bh[2]);
                    MMA_BF16(sc[2 * nt2 + 1], qh[ks], bh[1], bh[3]);
                    MMA_BF16(sc[2 * nt2 + 1], qh[ks], bl[1], bl[3]);
                    MMA_BF16(sc[2 * nt2 + 1], ql[ks], bh[1], bh[3]);
                }
            }

            for (int j = 0; j < ntiles; j++) {
                int gk = key0 + j * 8 + 2 * (l & 3);
                if (needmask) {
                    int dA0 = gqA - gk;     if (dA0 < 0) dA0 = -dA0;
                    int dA1 = gqA - gk - 1; if (dA1 < 0) dA1 = -dA1;
                    int dB0 = gqA + 8 - gk;     if (dB0 < 0) dB0 = -dB0;
                    int dB1 = gqA + 8 - gk - 1; if (dB1 < 0) dB1 = -dB1;
                    sc[j][0] = (dA0 <= WINR) ? sc[j][0] * ASCALE : -1e30f;
                    sc[j][1] = (dA1 <= WINR) ? sc[j][1] * ASCALE : -1e30f;
                    sc[j][2] = (dB0 <= WINR) ? sc[j][2] * ASCALE : -1e30f;
                    sc[j][3] = (dB1 <= WINR) ? sc[j][3] * ASCALE : -1e30f;
                } else if (ph == 1) {
                    bool ok = (j * 8 + 2 * (l & 3)) < 32;
                    sc[j][0] = ok ? sc[j][0] * ASCALE : -1e30f;
                    sc[j][1] = ok ? sc[j][1] * ASCALE : -1e30f;
                    sc[j][2] = ok ? sc[j][2] * ASCALE : -1e30f;
                    sc[j][3] = ok ? sc[j][3] * ASCALE : -1e30f;
                } else {
                    sc[j][0] *= ASCALE; sc[j][1] *= ASCALE;
                    sc[j][2] *= ASCALE; sc[j][3] *= ASCALE;
                }
            }

            float mxA = -1e30f, mxB = -1e30f;
            for (int j = 0; j < ntiles; j++) {
                mxA = fmaxf(mxA, fmaxf(sc[j][0], sc[j][1]));
                mxB = fmaxf(mxB, fmaxf(sc[j][2], sc[j][3]));
            }
            mxA = fmaxf(mxA, __shfl_xor_sync(0xffffffffu, mxA, 1));
            mxA = fmaxf(mxA, __shfl_xor_sync(0xffffffffu, mxA, 2));
            mxB = fmaxf(mxB, __shfl_xor_sync(0xffffffffu, mxB, 1));
            mxB = fmaxf(mxB, __shfl_xor_sync(0xffffffffu, mxB, 2));
            float nmA = fmaxf(mA, mxA), nmB = fmaxf(mB, mxB);
            float fA = __expf(mA - nmA), fB = __expf(mB - nmB);
            mA = nmA; mB = nmB;
            float sA = 0.f, sB = 0.f;
            for (int j = 0; j < ntiles; j++) {
                sc[j][0] = __expf(sc[j][0] - nmA);
                sc[j][1] = __expf(sc[j][1] - nmA);
                sc[j][2] = __expf(sc[j][2] - nmB);
                sc[j][3] = __expf(sc[j][3] - nmB);
                sA += sc[j][0] + sc[j][1];
                sB += sc[j][2] + sc[j][3];
            }
            sA += __shfl_xor_sync(0xffffffffu, sA, 1);
            sA += __shfl_xor_sync(0xffffffffu, sA, 2);
            sB += __shfl_xor_sync(0xffffffffu, sB, 1);
            sB += __shfl_xor_sync(0xffffffffu, sB, 2);
            lA = lA * fA + sA;
            lB = lB * fB + sB;
#pragma unroll
            for (int j = 0; j < 8; j++) {
                acc[j][0] *= fA; acc[j][1] *= fA;
                acc[j][2] *= fB; acc[j][3] *= fB;
            }

            for (int kt = 0; kt < nt2max; kt++) {
                uint32_t ah[4], al_[4];
                ah[0] = CVT2(sc[2 * kt][0], sc[2 * kt][1]);
                ah[1] = CVT2(sc[2 * kt][2], sc[2 * kt][3]);
                ah[2] = CVT2(sc[2 * kt + 1][0], sc[2 * kt + 1][1]);
                ah[3] = CVT2(sc[2 * kt + 1][2], sc[2 * kt + 1][3]);
                {
                    float2 r0 = __bfloat1622float2(*(__nv_bfloat162*)&ah[0]);
                    float2 r1 = __bfloat1622float2(*(__nv_bfloat162*)&ah[1]);
                    float2 r2 = __bfloat1622float2(*(__nv_bfloat162*)&ah[2]);
                    float2 r3 = __bfloat1622float2(*(__nv_bfloat162*)&ah[3]);
                    al_[0] = CVT2(sc[2 * kt][0] - r0.x, sc[2 * kt][1] - r0.y);
                    al_[1] = CVT2(sc[2 * kt][2] - r1.x, sc[2 * kt][3] - r1.y);
                    al_[2] = CVT2(sc[2 * kt + 1][0] - r2.x, sc[2 * kt + 1][1] - r2.y);
                    al_[3] = CVT2(sc[2 * kt + 1][2] - r3.x, sc[2 * kt + 1][3] - r3.y);
                }
                int vrow = kt * 16 + (l & 7) + ((l >> 3) & 1) * 8;
#pragma unroll
                for (int jn2 = 0; jn2 < 4; jn2++) {
                    int seg = jn2 * 2 + (l >> 4);
                    uint32_t off = vrow * 128 + ((seg ^ (vrow & 7)) << 4);
                    uint32_t bh[4], bl[4];
                    LDSM4T(bh, sVH + off);
                    LDSM4T(bl, sVL + off);
                    MMA_BF16(acc[2 * jn2], ah, bh[0], bh[1]);
                    MMA_BF16(acc[2 * jn2], ah, bl[0], bl[1]);
                    MMA_BF16(acc[2 * jn2], al_, bh[0], bh[1]);
                    MMA_BF16(acc[2 * jn2 + 1], ah, bh[2], bh[3]);
                    MMA_BF16(acc[2 * jn2 + 1], ah, bl[2], bl[3]);
                    MMA_BF16(acc[2 * jn2 + 1], al_, bh[2], bh[3]);
                }
            }
        }

        float invA = 1.f / lA, invB = 1.f / lB;
#pragma unroll
        for (int j = 0; j < 8; j++) {
            int hd = j * 8 + 2 * (l & 3);
            size_t offA = (hbase + gqA) * 64 + hd;
            size_t offB = offA + 8 * 64;
            float2 oA = make_float2(acc[j][0] * invA, acc[j][1] * invA);
            float2 oB = make_float2(acc[j][2] * invB, acc[j][3] * invB);
            if (ph > 0) {
                float2 pA = *(float2*)&O[offA]; oA.x += pA.x; oA.y += pA.y;
                float2 pB = *(float2*)&O[offB]; oB.x += pB.x; oB.y += pB.y;
            }
            *(float2*)&O[offA] = oA;
            *(float2*)&O[offB] = oB;
        }
    }
}

// ---------------------------------------------------------------------------
// out = fused(C) @ W^T + b via mma.sync bf16x3 (R14 version, fused A split).
// ---------------------------------------------------------------------------
#define OP_LDG_A(kc)                                                           \
    do {                                                                       \
        int _hh = (kc) >> 1;                                                   \
        int _hdb = ((kc) & 1) * 32;                                            \
        _Pragma("unroll")                                                      \
        for (int rep = 0; rep < 2; rep++) {                                    \
            int idx = t + rep * 256;                                           \
            int row = idx >> 2, seg = idx & 3;                                 \
            int m = m0 + row;                                                  \
            int bi = m >> 11, ni = m & 2047;                                   \
            const float* s = &C[((size_t)(bi * 16 + _hh) * 2048 + ni) * 64     \
                                + _hdb + seg * 8];                             \
            av[rep][0] = *(const float4*)s;                                    \
            av[rep][1] = *(const float4*)(s + 4);                              \
        }                                                                      \
    } while (0)

#define OP_STS_A(s)                                                            \
    do {                                                                       \
        _Pragma("unroll")                                                      \
        for (int rep = 0; rep < 2; rep++) {                                    \
            int idx = t + rep * 256;                                           \
            int row = idx >> 2, seg = idx & 3;                                 \
            uint32_t h0 = CVT2(av[rep][0].x, av[rep][0].y);                    \
            uint32_t h1 = CVT2(av[rep][0].z, av[rep][0].w);                    \
            uint32_t h2 = CVT2(av[rep][1].x, av[rep][1].y);                    \
            uint32_t h3 = CVT2(av[rep][1].z, av[rep][1].w);                    \
            float2 f0 = __bfloat1622float2(*(__nv_bfloat162*)&h0);             \
            float2 f1 = __bfloat1622float2(*(__nv_bfloat162*)&h1);             \
            float2 f2 = __bfloat1622float2(*(__nv_bfloat162*)&h2);             \
            float2 f3 = __bfloat1622float2(*(__nv_bfloat162*)&h3);             \
            uint32_t l0 = CVT2(av[rep][0].x - f0.x, av[rep][0].y - f0.y);      \
            uint32_t l1 = CVT2(av[rep][0].z - f1.x, av[rep][0].w - f1.y);      \
            uint32_t l2 = CVT2(av[rep][1].x - f2.x, av[rep][1].y - f2.y);      \
            uint32_t l3 = CVT2(av[rep][1].z - f3.x, av[rep][1].w - f3.y);      \
            uint32_t off = (s) * 40960 + row * 80 + seg * 16;                  \
            *(uint4*)(smc + off)         = make_uint4(h0, h1, h2, h3);         \
            *(uint4*)(smc + 10240 + off) = make_uint4(l0, l1, l2, l3);         \
        }                                                                      \
    } while (0)

#define OP_LOAD_W(kc, s)                                                       \
    do {                                                                       \
        uint32_t _base = sb + (s) * 40960 + 20480;                             \
        _Pragma("unroll")                                                      \
        for (int rep = 0; rep < 4; rep++) {                                    \
            int idx = t + rep * 256;                                           \
            int plane = idx >> 9;                                              \
            int rem = idx & 511;                                               \
            int row = rem >> 2, seg = rem & 3;                                 \
            uint32_t dst = _base + plane * 10240 + row * 80 + seg * 16;        \
            const __nv_bfloat16* src = plane ? Wlg : Whg;                      \
            CP_ASYNC16(dst, &src[(size_t)(n0 + row) * 1024 + (kc) * 32 + seg * 8]); \
        }                                                                      \
    } while (0)

__global__ __launch_bounds__(256, 2) void k_outproj_mma(const float* __restrict__ C,
                                                        const __nv_bfloat16* __restrict__ Whg,
                                                        const __nv_bfloat16* __restrict__ Wlg,
                                                        const float* __restrict__ bias,
                                                        float* __restrict__ out) {
    extern __shared__ char smc[];
    uint32_t sb = smem_u32(smc);
    int t = threadIdx.x;
    int wid = t >> 5, l = t & 31;
    int wm = wid & 3, wn = wid >> 2;
    int m0 = blockIdx.x * 128, n0 = blockIdx.y * 128;

    float acc[2][8][4] = {};
    float4 av[2][2];

    int row_a = wm * 32 + (l & 15);
    int sega  = (l >> 4);
    int row_b = wn * 64 + ((l >> 4) & 1) * 8 + (l & 7);
    int segb  = ((l >> 3) & 1);

    OP_LDG_A(0);
    OP_LOAD_W(0, 0);
    CP_COMMIT();

    for (int kc = 0; kc < 32; kc++) {
        OP_STS_A(kc & 1);
        if (kc + 1 < 32) {
            OP_LOAD_W(kc + 1, (kc + 1) & 1);
            CP_COMMIT();
            OP_LDG_A(kc + 1);
            CP_WAIT(1);
        } else {
            CP_WAIT(0);
        }
        __syncthreads();
        uint32_t base = sb + (kc & 1) * 40960;

#pragma unroll
        for (int ks = 0; ks < 2; ks++) {
            uint32_t ah[2][4], al_[2][4];
#pragma unroll
            for (int mt = 0; mt < 2; mt++) {
                int ra = row_a + mt * 16;
                uint32_t off = ra * 80 + (ks * 2 + sega) * 16;
                LDSM4(ah[mt], base + off);
                LDSM4(al_[mt], base + 10240 + off);
            }
#pragma unroll
            for (int ntp = 0; ntp < 4; ntp++) {
                int rb = row_b + ntp * 16;
                uint32_t off = rb * 80 + (ks * 2 + segb) * 16;
                uint32_t bh[4], bl[4];
                LDSM4(bh, base + 20480 + off);
                LDSM4(bl, base + 30720 + off);
#pragma unroll
                for (int mt = 0; mt < 2; mt++) {
#pragma unroll
                    for (int half = 0; half < 2; half++) {
                        float* d = acc[mt][ntp * 2 + half];
                        MMA_BF16(d, ah[mt], bh[half * 2], bh[half * 2 + 1]);
                        MMA_BF16(d, ah[mt], bl[half * 2], bl[half * 2 + 1]);
                        MMA_BF16(d, al_[mt], bh[half * 2], bh[half * 2 + 1]);
                    }
                }
            }
        }
        __syncthreads();
    }

#pragma unroll
    for (int mt = 0; mt < 2; mt++) {
        int r0 = m0 + wm * 32 + mt * 16 + (l >> 2);
#pragma unroll
        for (int nt = 0; nt < 8; nt++) {
            int c = n0 + wn * 64 + nt * 8 + 2 * (l & 3);
            float b0 = bias[c], b1 = bias[c + 1];
            float* d = acc[mt][nt];
            *(float2*)&out[(size_t)r0 * 1024 + c] = make_float2(d[0] + b0, d[1] + b1);
            *(float2*)&out[(size_t)(r0 + 8) * 1024 + c] = make_float2(d[2] + b0, d[3] + b1);
        }
    }
}

// ---------------------------------------------------------------------------
__global__ __launch_bounds__(128) void k_heads(const float* __restrict__ C,
                                               const float* __restrict__ tW, const float* __restrict__ tb,
                                               const float* __restrict__ iW, const float* __restrict__ ib,
                                               const float* __restrict__ cW, const float* __restrict__ cb,
                                               float* __restrict__ out) {
    int r = blockIdx.x;
    int b = r >> 11, n = r & 2047;
    __shared__ float last[64];
    int t = threadIdx.x;
    if (t < 64) last[t] = C[((size_t)(b * 16) * 2048 + n) * 64 + t];
    __syncthreads();
    if (t < 2) {
        float s = tb[t];
        for (int k = 0; k < 64; k++) s += last[k] * tW[t * 64 + k];
        out[4194304 + (size_t)r * 2 + t] = s;
    } else if (t < 66) {
        int j = t - 2;
        float s = ib[j];
        for (int k = 0; k < 64; k++) s += last[k] * iW[j * 64 + k];
        out[4202496 + (size_t)r * 64 + j] = s;
    } else if (t < 98) {
        int j = t - 66;
        float s = cb[j];
        for (int k = 0; k < 64; k++) s += last[k] * cW[j * 64 + k];
        out[4464640 + (size_t)r * 32 + j] = s;
    }
}

// ---------------------------------------------------------------------------
extern "C" void kernel_launch(void* const* d_in, const int* in_sizes, int n_in,
                              void* d_out, int out_size) {
    const float* x   = (const float*)d_in[0];
    const float* mem = (const float*)d_in[1];
    P3 Us  = { (const float*)d_in[2],  (const float*)d_in[8],  (const float*)d_in[14] };
    P3 Vs  = { (const float*)d_in[3],  (const float*)d_in[9],  (const float*)d_in[15] };
    P3 als = { (const float*)d_in[4],  (const float*)d_in[10], (const float*)d_in[16] };
    P3 As  = { (const float*)d_in[5],  (const float*)d_in[11], (const float*)d_in[17] };
    P3 Bls = { (const float*)d_in[6],  (const float*)d_in[12], (const float*)d_in[18] };
    P3 bis = { (const float*)d_in[7],  (const float*)d_in[13], (const float*)d_in[19] };
    const float* outW = (const float*)d_in[20];
    const float* outb = (const float*)d_in[21];
    const float* tW = (const float*)d_in[22];
    const float* tb = (const float*)d_in[23];
    const float* iW = (const float*)d_in[24];
    const float* ib = (const float*)d_in[25];
    const float* cW = (const float*)d_in[26];
    const float* cb = (const float*)d_in[27];
    float* out = (float*)d_out;

    void *pL, *pQKV, *pC, *pXh, *pXl, *pUth, *pUtl, *pTh, *pTl, *pVh, *pVl, *pWh, *pWl;
    cudaGetSymbolAddress(&pL, g_l);
    cudaGetSymbolAddress(&pQKV, g_qkv);
    cudaGetSymbolAddress(&pC, g_comb);
    cudaGetSymbolAddress(&pXh, g_xh);
    cudaGetSymbolAddress(&pXl, g_xl);
    cudaGetSymbolAddress(&pUth, g_uth);
    cudaGetSymbolAddress(&pUtl, g_utl);
    cudaGetSymbolAddress(&pTh, g_th);
    cudaGetSymbolAddress(&pTl, g_tl);
    cudaGetSymbolAddress(&pVh, g_vh);
    cudaGetSymbolAddress(&pVl, g_vl);
    cudaGetSymbolAddress(&pWh, g_wh);
    cudaGetSymbolAddress(&pWl, g_wl);
    float* Lb = (float*)pL;
    float* QKV = (float*)pQKV;
    float* Cb = (float*)pC;
    const size_t QSZ = (size_t)BATCH * NHEAD * NSEQ * 64;

    k_cvt_x<<<4096, 256>>>(x, (__nv_bfloat16*)pXh, (__nv_bfloat16*)pXl);
    k_lora<<<4096, 128>>>(x, As, Lb);
    k_cvt_w<<<1984, 256>>>(outW, Vs, Us,
                           (__nv_bfloat16*)pWh, (__nv_bfloat16*)pWl,
                           (__nv_bfloat16*)pVh, (__nv_bfloat16*)pVl,
                           (__nv_bfloat16*)pUth, (__nv_bfloat16*)pUtl);

    const int SMEM_XU = 61440;
    cudaFuncSetAttribute(k_xu_mma, cudaFuncAttributeMaxDynamicSharedMemorySize, SMEM_XU);
    k_xu_mma<<<dim3(32, 3), 256, SMEM_XU>>>((const __nv_bfloat16*)pXh,
                                            (const __nv_bfloat16*)pXl,
                                            (const __nv_bfloat16*)pUth,
                                            (const __nv_bfloat16*)pUtl,
                                            als,
                                            (__nv_bfloat16*)pTh, (__nv_bfloat16*)pTl);

    const int SMEM_PJ = 75776;
    cudaFuncSetAttribute(k_proj_mma, cudaFuncAttributeMaxDynamicSharedMemorySize, SMEM_PJ);
    k_proj_mma<<<dim3(32, 8, 3), 256, SMEM_PJ>>>((const __nv_bfloat16*)pTh,
                                                 (const __nv_bfloat16*)pTl,
                                                 (const __nv_bfloat16*)pVh,
                                                 (const __nv_bfloat16*)pVl,
                                                 Lb, Bls, bis, QKV);

    const int SMEM_ATTN = 32768;
    cudaFuncSetAttribute(k_attn_mma, cudaFuncAttributeMaxDynamicSharedMemorySize, SMEM_ATTN);
    k_attn_mma<<<dim3(32, 16, 2), 128, SMEM_ATTN>>>(QKV, QKV + QSZ, QKV + 2 * QSZ, mem, Cb);

    const int SMEM_OP = 81920;
    cudaFuncSetAttribute(k_outproj_mma, cudaFuncAttributeMaxDynamicSharedMemorySize, SMEM_OP);
    k_outproj_mma<<<dim3(32, 8), 256, SMEM_OP>>>(Cb,
                                                 (const __nv_bfloat16*)pWh,
                                                 (const __nv_bfloat16*)pWl,
                                                 outb, out);

    k_heads<<<4096, 128>>>(Cb, tW, tb, iW, ib, cW, cb, out);
}